// round 1
// baseline (speedup 1.0000x reference)
#include <cuda_runtime.h>
#include <cstdint>

// Problem dims
#define NB   512          // batch
#define TQ   128          // seq len
#define CD   384          // channels
#define HD   64           // head dim
#define MTOT (NB*TQ)      // 65536 rows for projection GEMM
#define SCALE 0.4082482904638631f   // 6^-0.5 (head_count**-0.5)

typedef unsigned long long ull;

// Scratch for Q, K, V (device globals; no allocation allowed)
__device__ float g_q[NB*TQ*HD];
__device__ float g_k[NB*TQ*HD];
__device__ float g_v[NB*TQ*HD];

// packed f32x2 helpers
__device__ __forceinline__ ull pk(float v) {
    unsigned u = __float_as_uint(v);
    return ((ull)u << 32) | (ull)u;
}
__device__ __forceinline__ void fma2(ull &d, ull a, ull b) {
    asm("fma.rn.f32x2 %0, %1, %2, %0;" : "+l"(d) : "l"(a), "l"(b));
}

// ============================================================================
// Kernel 1: fused QKV projection.
// C[M,192] = x[M,384] @ [Wq|Wk|Wv].  BM=64, BK=16, BN=192 (full).
// A tile stored in SMEM as duplicated f32x2 pairs so the inner loop is pure
// LDS.128 + fma.rn.f32x2 (no pack MOVs on the critical path).
// 256 threads: 16x16 grid, each thread computes 4 m-rows x (3 matrices x 4 cols).
// ============================================================================
__global__ __launch_bounds__(256) void proj_kernel(
    const float* __restrict__ x,
    const float* __restrict__ Wq,
    const float* __restrict__ Wk,
    const float* __restrict__ Wv)
{
    __shared__ ull   As[16][66];    // [k][m] duplicated pairs, padded stride
    __shared__ float Bs[16][196];   // [k][ 0:64 Wq | 64:128 Wk | 128:192 Wv ], padded

    const int tid = threadIdx.x;
    const int ty = tid >> 4;        // 0..15 -> m tile (4 rows each)
    const int tx = tid & 15;        // 0..15 -> n tile (4 cols per matrix)
    const int mBase = blockIdx.x * 64;

    ull acc[4][6];
    #pragma unroll
    for (int i = 0; i < 4; i++)
        #pragma unroll
        for (int j = 0; j < 6; j++) acc[i][j] = 0ull;  // (0.f,0.f)

    const int lm = tid >> 2;            // A-loader row 0..63
    const int lk = (tid & 3) * 4;       // A-loader k offset 0,4,8,12
    const int br = tid >> 4;            // B-loader row 0..15
    const int bc = (tid & 15) * 4;      // B-loader col 0..60

    for (int k0 = 0; k0 < CD; k0 += 16) {
        __syncthreads();  // previous compute done before overwriting tiles
        // load A tile 64x16 -> transposed + pair-duplicated
        float4 a = *(const float4*)(x + (size_t)(mBase + lm) * CD + k0 + lk);
        As[lk + 0][lm] = pk(a.x);
        As[lk + 1][lm] = pk(a.y);
        As[lk + 2][lm] = pk(a.z);
        As[lk + 3][lm] = pk(a.w);
        // load B tiles 16x64 per matrix
        *(float4*)&Bs[br][bc]       = *(const float4*)(Wq + (k0 + br) * HD + bc);
        *(float4*)&Bs[br][64 + bc]  = *(const float4*)(Wk + (k0 + br) * HD + bc);
        *(float4*)&Bs[br][128 + bc] = *(const float4*)(Wv + (k0 + br) * HD + bc);
        __syncthreads();

        #pragma unroll
        for (int kk = 0; kk < 16; kk++) {
            ulonglong2 a01 = *(const ulonglong2*)&As[kk][ty * 4];
            ulonglong2 a23 = *(const ulonglong2*)&As[kk][ty * 4 + 2];
            ull aM[4] = {a01.x, a01.y, a23.x, a23.y};
            ulonglong2 bq = *(const ulonglong2*)&Bs[kk][tx * 4];
            ulonglong2 bk = *(const ulonglong2*)&Bs[kk][64 + tx * 4];
            ulonglong2 bv = *(const ulonglong2*)&Bs[kk][128 + tx * 4];
            #pragma unroll
            for (int i = 0; i < 4; i++) {
                fma2(acc[i][0], aM[i], bq.x);
                fma2(acc[i][1], aM[i], bq.y);
                fma2(acc[i][2], aM[i], bk.x);
                fma2(acc[i][3], aM[i], bk.y);
                fma2(acc[i][4], aM[i], bv.x);
                fma2(acc[i][5], aM[i], bv.y);
            }
        }
    }

    // epilogue: 4 float4 stores per matrix
    #pragma unroll
    for (int i = 0; i < 4; i++) {
        size_t row = (size_t)(mBase + ty * 4 + i);
        *(ulonglong2*)(g_q + row * HD + tx * 4) = make_ulonglong2(acc[i][0], acc[i][1]);
        *(ulonglong2*)(g_k + row * HD + tx * 4) = make_ulonglong2(acc[i][2], acc[i][3]);
        *(ulonglong2*)(g_v + row * HD + tx * 4) = make_ulonglong2(acc[i][4], acc[i][5]);
    }
}

// ============================================================================
// Kernel 2: per-batch attention. One CTA per batch, 256 threads.
// SMEM: Q^T [64][132], K^T [64][132] (h-major for register-blocked QK^T),
//       V [128][68], S [128][132] stored [s][t] so softmax walks coalesced
//       and the PV GEMM reads S rows contiguously in t.
// ============================================================================
#define QK_STRIDE 132
#define V_STRIDE  68
#define SM_QST 0
#define SM_KST (64 * QK_STRIDE)
#define SM_VS  (2 * 64 * QK_STRIDE)
#define SM_S   (2 * 64 * QK_STRIDE + 128 * V_STRIDE)
#define ATTN_SMEM_BYTES ((2 * 64 * QK_STRIDE + 128 * V_STRIDE + 128 * QK_STRIDE) * 4)

__device__ __forceinline__ float warpMax(float v) {
    #pragma unroll
    for (int o = 16; o; o >>= 1) v = fmaxf(v, __shfl_xor_sync(0xffffffffu, v, o));
    return v;
}
__device__ __forceinline__ float warpSum(float v) {
    #pragma unroll
    for (int o = 16; o; o >>= 1) v += __shfl_xor_sync(0xffffffffu, v, o);
    return v;
}

__global__ __launch_bounds__(256) void attn_kernel(float* __restrict__ out)
{
    extern __shared__ float sm[];
    float* Qst = sm + SM_QST;
    float* Kst = sm + SM_KST;
    float* Vs  = sm + SM_VS;
    float* S   = sm + SM_S;

    const int tid = threadIdx.x;
    const int b = blockIdx.x;
    const float* qb = g_q + (size_t)b * TQ * HD;
    const float* kb = g_k + (size_t)b * TQ * HD;
    const float* vb = g_v + (size_t)b * TQ * HD;

    // Load Q, K transposed ([h][t]); V straight ([s][h]).
    for (int i = tid; i < TQ * (HD / 4); i += 256) {
        int row = i >> 4;           // 0..127
        int c4  = (i & 15) * 4;     // 0..60
        float4 q = *(const float4*)(qb + row * HD + c4);
        Qst[(c4 + 0) * QK_STRIDE + row] = q.x;
        Qst[(c4 + 1) * QK_STRIDE + row] = q.y;
        Qst[(c4 + 2) * QK_STRIDE + row] = q.z;
        Qst[(c4 + 3) * QK_STRIDE + row] = q.w;
        float4 k = *(const float4*)(kb + row * HD + c4);
        Kst[(c4 + 0) * QK_STRIDE + row] = k.x;
        Kst[(c4 + 1) * QK_STRIDE + row] = k.y;
        Kst[(c4 + 2) * QK_STRIDE + row] = k.z;
        Kst[(c4 + 3) * QK_STRIDE + row] = k.w;
        *(float4*)&Vs[row * V_STRIDE + c4] = *(const float4*)(vb + row * HD + c4);
    }
    __syncthreads();

    // Phase 1: S[s][t] = scale * q_t . k_s   (8t x 8s microtile per thread)
    {
        const int ty = tid >> 4, tx = tid & 15;
        const int t0 = ty * 8, s0 = tx * 8;
        ull acc[8][4];
        #pragma unroll
        for (int i = 0; i < 8; i++)
            #pragma unroll
            for (int p = 0; p < 4; p++) acc[i][p] = 0ull;

        #pragma unroll 8
        for (int h = 0; h < HD; h++) {
            const float* qr = &Qst[h * QK_STRIDE + t0];
            float4 q0 = *(const float4*)qr;
            float4 q1 = *(const float4*)(qr + 4);
            float qv[8] = {q0.x, q0.y, q0.z, q0.w, q1.x, q1.y, q1.z, q1.w};
            const ulonglong2* kr = (const ulonglong2*)&Kst[h * QK_STRIDE + s0];
            ulonglong2 kp0 = kr[0], kp1 = kr[1];
            #pragma unroll
            for (int i = 0; i < 8; i++) {
                ull ap = pk(qv[i]);
                fma2(acc[i][0], ap, kp0.x);
                fma2(acc[i][1], ap, kp0.y);
                fma2(acc[i][2], ap, kp1.x);
                fma2(acc[i][3], ap, kp1.y);
            }
        }
        #pragma unroll
        for (int i = 0; i < 8; i++)
            #pragma unroll
            for (int p = 0; p < 4; p++) {
                float lo = __uint_as_float((unsigned)acc[i][p]);
                float hi = __uint_as_float((unsigned)(acc[i][p] >> 32));
                S[(s0 + 2 * p)     * QK_STRIDE + t0 + i] = lo * SCALE;
                S[(s0 + 2 * p + 1) * QK_STRIDE + t0 + i] = hi * SCALE;
            }
    }
    __syncthreads();

    // Softmax per t-row (warp per row), causal mask s<=t, write back weights.
    {
        const int wid = tid >> 5, lane = tid & 31;
        const float NEG_INF = __int_as_float(0xff800000);
        for (int r = 0; r < 16; r++) {
            int t = r * 8 + wid;
            float v[4];
            #pragma unroll
            for (int j = 0; j < 4; j++) {
                int s = lane + 32 * j;
                v[j] = (s <= t) ? S[s * QK_STRIDE + t] : NEG_INF;
            }
            float m = fmaxf(fmaxf(v[0], v[1]), fmaxf(v[2], v[3]));
            m = warpMax(m);
            float p[4], sum = 0.f;
            #pragma unroll
            for (int j = 0; j < 4; j++) {
                int s = lane + 32 * j;
                p[j] = (s <= t) ? __expf(v[j] - m) : 0.f;
                sum += p[j];
            }
            sum = warpSum(sum);
            float inv = 1.0f / sum;
            #pragma unroll
            for (int j = 0; j < 4; j++) {
                int s = lane + 32 * j;
                S[s * QK_STRIDE + t] = p[j] * inv;
            }
        }
    }
    __syncthreads();

    // Phase 2: O[t][h] = sum_s S[s][t] * V[s][h]   (4t x 8h microtile)
    {
        const int ty = tid >> 3, tx = tid & 7;     // ty 0..31, tx 0..7
        const int t0 = ty * 4, h0 = tx * 8;
        ull acc[4][4];
        #pragma unroll
        for (int i = 0; i < 4; i++)
            #pragma unroll
            for (int p = 0; p < 4; p++) acc[i][p] = 0ull;

        #pragma unroll 8
        for (int s = 0; s < TQ; s++) {
            float4 w = *(const float4*)&S[s * QK_STRIDE + t0];
            float wv[4] = {w.x, w.y, w.z, w.w};
            const ulonglong2* vr = (const ulonglong2*)&Vs[s * V_STRIDE + h0];
            ulonglong2 v0 = vr[0], v1 = vr[1];
            #pragma unroll
            for (int i = 0; i < 4; i++) {
                ull ap = pk(wv[i]);
                fma2(acc[i][0], ap, v0.x);
                fma2(acc[i][1], ap, v0.y);
                fma2(acc[i][2], ap, v1.x);
                fma2(acc[i][3], ap, v1.y);
            }
        }
        float* ob = out + (size_t)b * TQ * HD;
        #pragma unroll
        for (int i = 0; i < 4; i++) {
            float* o = ob + (t0 + i) * HD + h0;
            *(ulonglong2*)o       = make_ulonglong2(acc[i][0], acc[i][1]);
            *(ulonglong2*)(o + 4) = make_ulonglong2(acc[i][2], acc[i][3]);
        }
    }
}

// ============================================================================
extern "C" void kernel_launch(void* const* d_in, const int* in_sizes, int n_in,
                              void* d_out, int out_size)
{
    (void)in_sizes; (void)n_in; (void)out_size;
    const float* x  = (const float*)d_in[0];
    const float* Wq = (const float*)d_in[1];
    const float* Wk = (const float*)d_in[2];
    const float* Wv = (const float*)d_in[3];
    float* out = (float*)d_out;

    cudaFuncSetAttribute(attn_kernel,
                         cudaFuncAttributeMaxDynamicSharedMemorySize,
                         ATTN_SMEM_BYTES);

    proj_kernel<<<MTOT / 64, 256>>>(x, Wq, Wk, Wv);
    attn_kernel<<<NB, 256, ATTN_SMEM_BYTES>>>(out);
}

// round 2
// speedup vs baseline: 1.0963x; 1.0963x over previous
#include <cuda_runtime.h>
#include <cstdint>

// Problem dims
#define NB   512          // batch
#define TQ   128          // seq len
#define CD   384          // channels
#define HD   64           // head dim
#define MTOT (NB*TQ)      // 65536 rows for projection GEMM
#define SCALE 0.4082482904638631f   // 6^-0.5 (head_count**-0.5)

typedef unsigned long long ull;

// Scratch for Q, K, V (device globals; no allocation allowed)
__device__ float g_q[NB*TQ*HD];
__device__ float g_k[NB*TQ*HD];
__device__ float g_v[NB*TQ*HD];

// ============================================================================
// Kernel 1: fused QKV projection via tf32 tensor cores (3xTF32 for fp32 acc).
// C[M,64] = x[M,384] @ W[384,64], one W (q/k/v) per blockIdx.y.
// BM=128, BN=64, BK=32. cp.async double-buffered. 8 warps -> 4x2 grid of
// 32x32 warp tiles; mma.sync.m16n8k8.row.col.f32.tf32.tf32.f32.
// ============================================================================
#define BM 128
#define BN 64
#define BK 32
#define AST 36   // A smem row stride in floats (36 % 32 == 4 -> conflict-free frags)
#define BST 68   // B smem row stride in floats (68 % 32 == 4)
#define PROJ_SMEM ((2*BM*AST + 2*BK*BST)*4)

__device__ __forceinline__ uint32_t f2tf(float x) {
    uint32_t r; asm("cvt.rna.tf32.f32 %0, %1;" : "=r"(r) : "f"(x)); return r;
}
__device__ __forceinline__ void mma_tf32(float* d,
    uint32_t a0, uint32_t a1, uint32_t a2, uint32_t a3,
    uint32_t b0, uint32_t b1)
{
    asm("mma.sync.aligned.m16n8k8.row.col.f32.tf32.tf32.f32 "
        "{%0,%1,%2,%3}, {%4,%5,%6,%7}, {%8,%9}, {%0,%1,%2,%3};"
        : "+f"(d[0]), "+f"(d[1]), "+f"(d[2]), "+f"(d[3])
        : "r"(a0), "r"(a1), "r"(a2), "r"(a3), "r"(b0), "r"(b1));
}
__device__ __forceinline__ void cp16(uint32_t s, const void* g) {
    asm volatile("cp.async.cg.shared.global [%0], [%1], 16;" :: "r"(s), "l"(g));
}

__global__ __launch_bounds__(256, 2) void proj_kernel(
    const float* __restrict__ x,
    const float* __restrict__ Wq,
    const float* __restrict__ Wk,
    const float* __restrict__ Wv)
{
    extern __shared__ float ps[];
    float* As = ps;                  // [2][BM*AST]
    float* Bs = ps + 2 * BM * AST;   // [2][BK*BST]

    const int tid = threadIdx.x;
    const int mBase = blockIdx.x * BM;
    const int y = blockIdx.y;
    const float* W = (y == 0) ? Wq : (y == 1) ? Wk : Wv;

    const uint32_t sA = (uint32_t)__cvta_generic_to_shared(As);
    const uint32_t sB = (uint32_t)__cvta_generic_to_shared(Bs);

    // global->smem loader coords
    const int arow = tid >> 1;               // 0..127
    const int acol = (tid & 1) * 16;         // 0 or 16
    const float* agp = x + (size_t)(mBase + arow) * CD + acol;
    const int bidx = tid * 2;
    const int brow = bidx >> 4;              // 0..31
    const int bcol = (bidx & 15) * 4;        // 0..56 step 8 (2 chunks: +0,+4)
    const float* bgp = W + brow * HD + bcol;

#define LOAD_TILES(buf, k0) do {                                          \
    uint32_t a_s = sA + (uint32_t)(((buf)*BM*AST + arow*AST + acol) * 4); \
    const float* a_g = agp + (k0);                                        \
    cp16(a_s,      a_g);     cp16(a_s + 16, a_g + 4);                     \
    cp16(a_s + 32, a_g + 8); cp16(a_s + 48, a_g + 12);                    \
    uint32_t b_s = sB + (uint32_t)(((buf)*BK*BST + brow*BST + bcol) * 4); \
    const float* b_g = bgp + (size_t)(k0) * HD;                           \
    cp16(b_s, b_g); cp16(b_s + 16, b_g + 4);                              \
    asm volatile("cp.async.commit_group;" ::: "memory");                  \
} while (0)

    const int lane = tid & 31;
    const int wid  = tid >> 5;
    const int wm = (wid & 3) * 32;   // warp m offset
    const int wn = (wid >> 2) * 32;  // warp n offset
    const int gr = lane >> 2;        // group row 0..7
    const int tg = lane & 3;         // thread-in-group 0..3

    float acc[2][4][4];
    #pragma unroll
    for (int mt = 0; mt < 2; mt++)
        #pragma unroll
        for (int nt = 0; nt < 4; nt++)
            #pragma unroll
            for (int i = 0; i < 4; i++) acc[mt][nt][i] = 0.f;

    LOAD_TILES(0, 0);

    for (int kb = 0; kb < CD / BK; kb++) {
        const int cur = kb & 1;
        if (kb < CD / BK - 1) {
            LOAD_TILES(cur ^ 1, (kb + 1) * BK);
            asm volatile("cp.async.wait_group 1;" ::: "memory");
        } else {
            asm volatile("cp.async.wait_group 0;" ::: "memory");
        }
        __syncthreads();

        const float* Ac = As + cur * BM * AST;
        const float* Bc = Bs + cur * BK * BST;

        #pragma unroll
        for (int kk = 0; kk < BK / 8; kk++) {
            uint32_t ah[2][4], al[2][4];
            #pragma unroll
            for (int mt = 0; mt < 2; mt++) {
                const float* p = Ac + (wm + mt * 16 + gr) * AST + kk * 8 + tg;
                float a0 = p[0], a2 = p[4];
                float a1 = p[8 * AST], a3 = p[8 * AST + 4];
                ah[mt][0] = f2tf(a0); al[mt][0] = f2tf(a0 - __uint_as_float(ah[mt][0]));
                ah[mt][1] = f2tf(a1); al[mt][1] = f2tf(a1 - __uint_as_float(ah[mt][1]));
                ah[mt][2] = f2tf(a2); al[mt][2] = f2tf(a2 - __uint_as_float(ah[mt][2]));
                ah[mt][3] = f2tf(a3); al[mt][3] = f2tf(a3 - __uint_as_float(ah[mt][3]));
            }
            uint32_t bh[4][2], bl[4][2];
            #pragma unroll
            for (int nt = 0; nt < 4; nt++) {
                const float* p = Bc + (kk * 8 + tg) * BST + wn + nt * 8 + gr;
                float b0 = p[0], b1 = p[4 * BST];
                bh[nt][0] = f2tf(b0); bl[nt][0] = f2tf(b0 - __uint_as_float(bh[nt][0]));
                bh[nt][1] = f2tf(b1); bl[nt][1] = f2tf(b1 - __uint_as_float(bh[nt][1]));
            }
            #pragma unroll
            for (int mt = 0; mt < 2; mt++)
                #pragma unroll
                for (int nt = 0; nt < 4; nt++) {
                    mma_tf32(acc[mt][nt], ah[mt][0], ah[mt][1], ah[mt][2], ah[mt][3],
                             bh[nt][0], bh[nt][1]);
                    mma_tf32(acc[mt][nt], ah[mt][0], ah[mt][1], ah[mt][2], ah[mt][3],
                             bl[nt][0], bl[nt][1]);
                    mma_tf32(acc[mt][nt], al[mt][0], al[mt][1], al[mt][2], al[mt][3],
                             bh[nt][0], bh[nt][1]);
                }
        }
        __syncthreads();
    }

    float* O = (y == 0) ? g_q : (y == 1) ? g_k : g_v;
    #pragma unroll
    for (int mt = 0; mt < 2; mt++)
        #pragma unroll
        for (int nt = 0; nt < 4; nt++) {
            int r0 = mBase + wm + mt * 16 + gr;
            int c0 = wn + nt * 8 + 2 * tg;
            *(float2*)(O + (size_t)r0 * HD + c0) =
                make_float2(acc[mt][nt][0], acc[mt][nt][1]);
            *(float2*)(O + (size_t)(r0 + 8) * HD + c0) =
                make_float2(acc[mt][nt][2], acc[mt][nt][3]);
        }
}

// packed f32x2 helpers (attention kernel)
__device__ __forceinline__ ull pk(float v) {
    unsigned u = __float_as_uint(v);
    return ((ull)u << 32) | (ull)u;
}
__device__ __forceinline__ void fma2(ull &d, ull a, ull b) {
    asm("fma.rn.f32x2 %0, %1, %2, %0;" : "+l"(d) : "l"(a), "l"(b));
}

// ============================================================================
// Kernel 2: per-batch attention (unchanged from R1). One CTA per batch.
// ============================================================================
#define QK_STRIDE 132
#define V_STRIDE  68
#define SM_QST 0
#define SM_KST (64 * QK_STRIDE)
#define SM_VS  (2 * 64 * QK_STRIDE)
#define SM_S   (2 * 64 * QK_STRIDE + 128 * V_STRIDE)
#define ATTN_SMEM_BYTES ((2 * 64 * QK_STRIDE + 128 * V_STRIDE + 128 * QK_STRIDE) * 4)

__device__ __forceinline__ float warpMax(float v) {
    #pragma unroll
    for (int o = 16; o; o >>= 1) v = fmaxf(v, __shfl_xor_sync(0xffffffffu, v, o));
    return v;
}
__device__ __forceinline__ float warpSum(float v) {
    #pragma unroll
    for (int o = 16; o; o >>= 1) v += __shfl_xor_sync(0xffffffffu, v, o);
    return v;
}

__global__ __launch_bounds__(256) void attn_kernel(float* __restrict__ out)
{
    extern __shared__ float sm[];
    float* Qst = sm + SM_QST;
    float* Kst = sm + SM_KST;
    float* Vs  = sm + SM_VS;
    float* S   = sm + SM_S;

    const int tid = threadIdx.x;
    const int b = blockIdx.x;
    const float* qb = g_q + (size_t)b * TQ * HD;
    const float* kb = g_k + (size_t)b * TQ * HD;
    const float* vb = g_v + (size_t)b * TQ * HD;

    for (int i = tid; i < TQ * (HD / 4); i += 256) {
        int row = i >> 4;
        int c4  = (i & 15) * 4;
        float4 q = *(const float4*)(qb + row * HD + c4);
        Qst[(c4 + 0) * QK_STRIDE + row] = q.x;
        Qst[(c4 + 1) * QK_STRIDE + row] = q.y;
        Qst[(c4 + 2) * QK_STRIDE + row] = q.z;
        Qst[(c4 + 3) * QK_STRIDE + row] = q.w;
        float4 k = *(const float4*)(kb + row * HD + c4);
        Kst[(c4 + 0) * QK_STRIDE + row] = k.x;
        Kst[(c4 + 1) * QK_STRIDE + row] = k.y;
        Kst[(c4 + 2) * QK_STRIDE + row] = k.z;
        Kst[(c4 + 3) * QK_STRIDE + row] = k.w;
        *(float4*)&Vs[row * V_STRIDE + c4] = *(const float4*)(vb + row * HD + c4);
    }
    __syncthreads();

    {
        const int ty = tid >> 4, tx = tid & 15;
        const int t0 = ty * 8, s0 = tx * 8;
        ull acc[8][4];
        #pragma unroll
        for (int i = 0; i < 8; i++)
            #pragma unroll
            for (int p = 0; p < 4; p++) acc[i][p] = 0ull;

        #pragma unroll 8
        for (int h = 0; h < HD; h++) {
            const float* qr = &Qst[h * QK_STRIDE + t0];
            float4 q0 = *(const float4*)qr;
            float4 q1 = *(const float4*)(qr + 4);
            float qv[8] = {q0.x, q0.y, q0.z, q0.w, q1.x, q1.y, q1.z, q1.w};
            const ulonglong2* kr = (const ulonglong2*)&Kst[h * QK_STRIDE + s0];
            ulonglong2 kp0 = kr[0], kp1 = kr[1];
            #pragma unroll
            for (int i = 0; i < 8; i++) {
                ull ap = pk(qv[i]);
                fma2(acc[i][0], ap, kp0.x);
                fma2(acc[i][1], ap, kp0.y);
                fma2(acc[i][2], ap, kp1.x);
                fma2(acc[i][3], ap, kp1.y);
            }
        }
        #pragma unroll
        for (int i = 0; i < 8; i++)
            #pragma unroll
            for (int p = 0; p < 4; p++) {
                float lo = __uint_as_float((unsigned)acc[i][p]);
                float hi = __uint_as_float((unsigned)(acc[i][p] >> 32));
                S[(s0 + 2 * p)     * QK_STRIDE + t0 + i] = lo * SCALE;
                S[(s0 + 2 * p + 1) * QK_STRIDE + t0 + i] = hi * SCALE;
            }
    }
    __syncthreads();

    {
        const int wid = tid >> 5, lane = tid & 31;
        const float NEG_INF = __int_as_float(0xff800000);
        for (int r = 0; r < 16; r++) {
            int t = r * 8 + wid;
            float v[4];
            #pragma unroll
            for (int j = 0; j < 4; j++) {
                int s = lane + 32 * j;
                v[j] = (s <= t) ? S[s * QK_STRIDE + t] : NEG_INF;
            }
            float m = fmaxf(fmaxf(v[0], v[1]), fmaxf(v[2], v[3]));
            m = warpMax(m);
            float p[4], sum = 0.f;
            #pragma unroll
            for (int j = 0; j < 4; j++) {
                int s = lane + 32 * j;
                p[j] = (s <= t) ? __expf(v[j] - m) : 0.f;
                sum += p[j];
            }
            sum = warpSum(sum);
            float inv = 1.0f / sum;
            #pragma unroll
            for (int j = 0; j < 4; j++) {
                int s = lane + 32 * j;
                S[s * QK_STRIDE + t] = p[j] * inv;
            }
        }
    }
    __syncthreads();

    {
        const int ty = tid >> 3, tx = tid & 7;
        const int t0 = ty * 4, h0 = tx * 8;
        ull acc[4][4];
        #pragma unroll
        for (int i = 0; i < 4; i++)
            #pragma unroll
            for (int p = 0; p < 4; p++) acc[i][p] = 0ull;

        #pragma unroll 8
        for (int s = 0; s < TQ; s++) {
            float4 w = *(const float4*)&S[s * QK_STRIDE + t0];
            float wv[4] = {w.x, w.y, w.z, w.w};
            const ulonglong2* vr = (const ulonglong2*)&Vs[s * V_STRIDE + h0];
            ulonglong2 v0 = vr[0], v1 = vr[1];
            #pragma unroll
            for (int i = 0; i < 4; i++) {
                ull ap = pk(wv[i]);
                fma2(acc[i][0], ap, v0.x);
                fma2(acc[i][1], ap, v0.y);
                fma2(acc[i][2], ap, v1.x);
                fma2(acc[i][3], ap, v1.y);
            }
        }
        float* ob = out + (size_t)b * TQ * HD;
        #pragma unroll
        for (int i = 0; i < 4; i++) {
            float* o = ob + (t0 + i) * HD + h0;
            *(ulonglong2*)o       = make_ulonglong2(acc[i][0], acc[i][1]);
            *(ulonglong2*)(o + 4) = make_ulonglong2(acc[i][2], acc[i][3]);
        }
    }
}

// ============================================================================
extern "C" void kernel_launch(void* const* d_in, const int* in_sizes, int n_in,
                              void* d_out, int out_size)
{
    (void)in_sizes; (void)n_in; (void)out_size;
    const float* x  = (const float*)d_in[0];
    const float* Wq = (const float*)d_in[1];
    const float* Wk = (const float*)d_in[2];
    const float* Wv = (const float*)d_in[3];
    float* out = (float*)d_out;

    cudaFuncSetAttribute(proj_kernel,
                         cudaFuncAttributeMaxDynamicSharedMemorySize,
                         PROJ_SMEM);
    cudaFuncSetAttribute(attn_kernel,
                         cudaFuncAttributeMaxDynamicSharedMemorySize,
                         ATTN_SMEM_BYTES);

    proj_kernel<<<dim3(MTOT / BM, 3), 256, PROJ_SMEM>>>(x, Wq, Wk, Wv);
    attn_kernel<<<NB, 256, ATTN_SMEM_BYTES>>>(out);
}

// round 3
// speedup vs baseline: 1.3821x; 1.2606x over previous
#include <cuda_runtime.h>
#include <cstdint>

// Problem dims
#define NB   512
#define TQ   128
#define CD   384
#define HD   64
#define MTOT (NB*TQ)
#define SCALE 0.4082482904638631f   // 6^-0.5

// Scratch (device globals; no allocation allowed)
__device__ float g_q[NB*TQ*HD];
__device__ float g_k[NB*TQ*HD];
__device__ float g_v[NB*TQ*HD];

// ---------------- tf32 helpers ----------------
__device__ __forceinline__ uint32_t f2tf(float x) {
    uint32_t r; asm("cvt.rna.tf32.f32 %0, %1;" : "=r"(r) : "f"(x)); return r;
}
__device__ __forceinline__ void mma_tf32(float* d,
    uint32_t a0, uint32_t a1, uint32_t a2, uint32_t a3,
    uint32_t b0, uint32_t b1)
{
    asm("mma.sync.aligned.m16n8k8.row.col.f32.tf32.tf32.f32 "
        "{%0,%1,%2,%3}, {%4,%5,%6,%7}, {%8,%9}, {%0,%1,%2,%3};"
        : "+f"(d[0]), "+f"(d[1]), "+f"(d[2]), "+f"(d[3])
        : "r"(a0), "r"(a1), "r"(a2), "r"(a3), "r"(b0), "r"(b1));
}
__device__ __forceinline__ void cp16(uint32_t s, const void* g) {
    asm volatile("cp.async.cg.shared.global [%0], [%1], 16;" :: "r"(s), "l"(g));
}
// split fp32 -> (hi, lo) tf32
__device__ __forceinline__ void split2(float x, uint32_t& h, uint32_t& l) {
    h = f2tf(x);
    l = f2tf(x - __uint_as_float(h));
}

// ============================================================================
// Kernel 1: fused QKV projection (x read once, A-frags converted once).
// C[M,192] = x[M,384] @ [Wq|Wk|Wv].  BM=128, BN=192, BK=16.
// 512 threads, 16 warps -> 4(m) x 4(n) warp grid, each warp 32x48.
// 3xTF32 via mma.sync.m16n8k8.
// ============================================================================
#define PAST 20     // A smem stride (16+4)
#define PBST 196    // B smem stride (192+4)
#define PROJ_SMEM ((2*128*PAST + 2*16*PBST)*4)

__global__ __launch_bounds__(512) void proj_kernel(
    const float* __restrict__ x,
    const float* __restrict__ Wq,
    const float* __restrict__ Wk,
    const float* __restrict__ Wv)
{
    extern __shared__ float ps[];
    float* As = ps;                    // [2][128*PAST]
    float* Bs = ps + 2 * 128 * PAST;   // [2][16*PBST]

    const int tid = threadIdx.x;
    const int mBase = blockIdx.x * 128;

    const uint32_t sA = (uint32_t)__cvta_generic_to_shared(As);
    const uint32_t sB = (uint32_t)__cvta_generic_to_shared(Bs);

    // A loader: 128 rows x 16 floats = 512 chunks of 4 -> 1 per thread
    const int arow = tid >> 2;
    const int acol = (tid & 3) * 4;
    const float* agp = x + (size_t)(mBase + arow) * CD + acol;

    // B loader: 16 rows x 192 floats = 768 chunks of 4 -> 1.5 per thread
    const float* Wm[3] = {Wq, Wk, Wv};

#define PLOAD(buf, k0) do {                                                   \
    cp16(sA + (uint32_t)(((buf)*128*PAST + arow*PAST + acol) * 4),            \
         agp + (k0));                                                         \
    _Pragma("unroll")                                                         \
    for (int j = 0; j < 2; j++) {                                             \
        int idx = tid + j * 512;                                              \
        if (idx < 768) {                                                      \
            int row = idx / 48;                                               \
            int cc  = (idx % 48) * 4;                                         \
            const float* src = Wm[cc >> 6] + (size_t)((k0) + row) * HD + (cc & 63); \
            cp16(sB + (uint32_t)(((buf)*16*PBST + row*PBST + cc) * 4), src);  \
        }                                                                     \
    }                                                                         \
    asm volatile("cp.async.commit_group;" ::: "memory");                      \
} while (0)

    const int lane = tid & 31;
    const int wid  = tid >> 5;
    const int wm = (wid & 3) * 32;
    const int wn = (wid >> 2) * 48;
    const int gr = lane >> 2;
    const int tg = lane & 3;

    float acc[2][6][4];
    #pragma unroll
    for (int mt = 0; mt < 2; mt++)
        #pragma unroll
        for (int nt = 0; nt < 6; nt++)
            #pragma unroll
            for (int i = 0; i < 4; i++) acc[mt][nt][i] = 0.f;

    PLOAD(0, 0);

    for (int kb = 0; kb < CD / 16; kb++) {
        const int cur = kb & 1;
        if (kb < CD / 16 - 1) {
            PLOAD(cur ^ 1, (kb + 1) * 16);
            asm volatile("cp.async.wait_group 1;" ::: "memory");
        } else {
            asm volatile("cp.async.wait_group 0;" ::: "memory");
        }
        __syncthreads();

        const float* Ac = As + cur * 128 * PAST;
        const float* Bc = Bs + cur * 16 * PBST;

        #pragma unroll
        for (int kk = 0; kk < 2; kk++) {
            uint32_t ah[2][4], al[2][4];
            #pragma unroll
            for (int mt = 0; mt < 2; mt++) {
                const float* p = Ac + (wm + mt * 16 + gr) * PAST + kk * 8 + tg;
                split2(p[0],           ah[mt][0], al[mt][0]);
                split2(p[8 * PAST],    ah[mt][1], al[mt][1]);
                split2(p[4],           ah[mt][2], al[mt][2]);
                split2(p[8 * PAST + 4],ah[mt][3], al[mt][3]);
            }
            #pragma unroll
            for (int nt = 0; nt < 6; nt++) {
                const float* p = Bc + (kk * 8 + tg) * PBST + wn + nt * 8 + gr;
                uint32_t bh0, bl0, bh1, bl1;
                split2(p[0],        bh0, bl0);
                split2(p[4 * PBST], bh1, bl1);
                #pragma unroll
                for (int mt = 0; mt < 2; mt++) {
                    mma_tf32(acc[mt][nt], ah[mt][0], ah[mt][1], ah[mt][2], ah[mt][3], bh0, bh1);
                    mma_tf32(acc[mt][nt], ah[mt][0], ah[mt][1], ah[mt][2], ah[mt][3], bl0, bl1);
                    mma_tf32(acc[mt][nt], al[mt][0], al[mt][1], al[mt][2], al[mt][3], bh0, bh1);
                }
            }
        }
        __syncthreads();
    }

    // epilogue
    #pragma unroll
    for (int nt = 0; nt < 6; nt++) {
        int n = wn + nt * 8;
        float* O = (n < 64) ? g_q : (n < 128) ? g_k : g_v;
        int c0 = (n & 63) + 2 * tg;
        #pragma unroll
        for (int mt = 0; mt < 2; mt++) {
            int r0 = mBase + wm + mt * 16 + gr;
            *(float2*)(O + (size_t)r0 * HD + c0) =
                make_float2(acc[mt][nt][0], acc[mt][nt][1]);
            *(float2*)(O + (size_t)(r0 + 8) * HD + c0) =
                make_float2(acc[mt][nt][2], acc[mt][nt][3]);
        }
    }
}

// ============================================================================
// Kernel 2: per-batch attention, all-tensor-core, no S smem.
// 8 warps; warp w owns t-rows [16w, 16w+16). S fragments live in registers,
// softmax via quad shuffles, P re-shaped to MMA A-frags via shuffles.
// Causal skip at 8-col tile granularity halves both GEMMs.
// smem = Q[128][68] + K[128][68] + V[128][67] = 104 KB -> 2 CTAs/SM.
// ============================================================================
#define QST 68
#define VST 67
#define ATTN_SMEM ((2*128*QST + 128*VST)*4)

__global__ __launch_bounds__(256, 2) void attn_kernel(float* __restrict__ out)
{
    extern __shared__ float sm[];
    float* Qs = sm;
    float* Ks = sm + 128 * QST;
    float* Vs = sm + 2 * 128 * QST;

    const int tid = threadIdx.x;
    const int b = blockIdx.x;
    const float* qb = g_q + (size_t)b * TQ * HD;
    const float* kb = g_k + (size_t)b * TQ * HD;
    const float* vb = g_v + (size_t)b * TQ * HD;

    // load Q,K (stride 68), V (stride 67)
    for (int i = tid; i < TQ * (HD / 4); i += 256) {
        int row = i >> 4;
        int c4  = (i & 15) * 4;
        float4 q = *(const float4*)(qb + row * HD + c4);
        Qs[row * QST + c4 + 0] = q.x; Qs[row * QST + c4 + 1] = q.y;
        Qs[row * QST + c4 + 2] = q.z; Qs[row * QST + c4 + 3] = q.w;
        float4 k = *(const float4*)(kb + row * HD + c4);
        Ks[row * QST + c4 + 0] = k.x; Ks[row * QST + c4 + 1] = k.y;
        Ks[row * QST + c4 + 2] = k.z; Ks[row * QST + c4 + 3] = k.w;
        float4 v = *(const float4*)(vb + row * HD + c4);
        Vs[row * VST + c4 + 0] = v.x; Vs[row * VST + c4 + 1] = v.y;
        Vs[row * VST + c4 + 2] = v.z; Vs[row * VST + c4 + 3] = v.w;
    }
    __syncthreads();

    const int w = tid >> 5, lane = tid & 31;
    const int gr = lane >> 2, tg = lane & 3;
    const int t0 = 16 * w;
    const int NT = 2 * w + 2;        // causal: s-tiles 0..NT-1 needed
    const int r0 = t0 + gr, r1 = r0 + 8;

    // ---- QK^T: S[t][s] fragments in registers ----
    float acc[16][4];
    #pragma unroll
    for (int nt = 0; nt < 16; nt++)
        #pragma unroll
        for (int i = 0; i < 4; i++) acc[nt][i] = 0.f;

    #pragma unroll
    for (int kk = 0; kk < 8; kk++) {
        const float* qp = Qs + (t0 + gr) * QST + kk * 8 + tg;
        uint32_t ah[4], al[4];
        split2(qp[0],           ah[0], al[0]);
        split2(qp[8 * QST],     ah[1], al[1]);
        split2(qp[4],           ah[2], al[2]);
        split2(qp[8 * QST + 4], ah[3], al[3]);
        #pragma unroll
        for (int nt = 0; nt < 16; nt++) {
            if (nt < NT) {
                const float* kp = Ks + (nt * 8 + gr) * QST + kk * 8 + tg;
                uint32_t bh0, bl0, bh1, bl1;
                split2(kp[0], bh0, bl0);
                split2(kp[4], bh1, bl1);
                mma_tf32(acc[nt], ah[0], ah[1], ah[2], ah[3], bh0, bh1);
                mma_tf32(acc[nt], ah[0], ah[1], ah[2], ah[3], bl0, bl1);
                mma_tf32(acc[nt], al[0], al[1], al[2], al[3], bh0, bh1);
            }
        }
    }

    // ---- softmax in registers (rows r0 via slots 0,1; r1 via slots 2,3) ----
    const float NEG = __int_as_float(0xff800000);
    float mx0 = NEG, mx1 = NEG;
    #pragma unroll
    for (int nt = 0; nt < 16; nt++) {
        if (nt < NT) {
            int c = nt * 8 + 2 * tg;
            float v0 = (c     <= r0) ? acc[nt][0] * SCALE : NEG;
            float v1 = (c + 1 <= r0) ? acc[nt][1] * SCALE : NEG;
            float v2 = (c     <= r1) ? acc[nt][2] * SCALE : NEG;
            float v3 = (c + 1 <= r1) ? acc[nt][3] * SCALE : NEG;
            acc[nt][0] = v0; acc[nt][1] = v1; acc[nt][2] = v2; acc[nt][3] = v3;
            mx0 = fmaxf(mx0, fmaxf(v0, v1));
            mx1 = fmaxf(mx1, fmaxf(v2, v3));
        }
    }
    mx0 = fmaxf(mx0, __shfl_xor_sync(0xffffffffu, mx0, 1));
    mx0 = fmaxf(mx0, __shfl_xor_sync(0xffffffffu, mx0, 2));
    mx1 = fmaxf(mx1, __shfl_xor_sync(0xffffffffu, mx1, 1));
    mx1 = fmaxf(mx1, __shfl_xor_sync(0xffffffffu, mx1, 2));

    float s0 = 0.f, s1 = 0.f;
    #pragma unroll
    for (int nt = 0; nt < 16; nt++) {
        if (nt < NT) {
            float p0 = __expf(acc[nt][0] - mx0);   // exp(-inf)=0 handles mask
            float p1 = __expf(acc[nt][1] - mx0);
            float p2 = __expf(acc[nt][2] - mx1);
            float p3 = __expf(acc[nt][3] - mx1);
            acc[nt][0] = p0; acc[nt][1] = p1; acc[nt][2] = p2; acc[nt][3] = p3;
            s0 += p0 + p1;  s1 += p2 + p3;
        }
    }
    s0 += __shfl_xor_sync(0xffffffffu, s0, 1);
    s0 += __shfl_xor_sync(0xffffffffu, s0, 2);
    s1 += __shfl_xor_sync(0xffffffffu, s1, 1);
    s1 += __shfl_xor_sync(0xffffffffu, s1, 2);
    const float i0 = 1.0f / s0, i1 = 1.0f / s1;
    #pragma unroll
    for (int nt = 0; nt < 16; nt++) {
        if (nt < NT) {
            acc[nt][0] *= i0; acc[nt][1] *= i0;
            acc[nt][2] *= i1; acc[nt][3] *= i1;
        }
    }

    // ---- PV: O[t][h] += P[t][s] * V[s][h]; P frags from acc via quad shuffle ----
    float oacc[8][4];
    #pragma unroll
    for (int nt = 0; nt < 8; nt++)
        #pragma unroll
        for (int i = 0; i < 4; i++) oacc[nt][i] = 0.f;

    const int qbase = lane & ~3;
    const int srcA = qbase + (tg >> 1);
    const int srcB = srcA + 2;
    const bool odd = tg & 1;

    #pragma unroll
    for (int kk = 0; kk < 16; kk++) {
        if (kk < NT) {
            float e0 = __shfl_sync(0xffffffffu, acc[kk][0], srcA);
            float o0 = __shfl_sync(0xffffffffu, acc[kk][1], srcA);
            float e1 = __shfl_sync(0xffffffffu, acc[kk][2], srcA);
            float o1 = __shfl_sync(0xffffffffu, acc[kk][3], srcA);
            float e2 = __shfl_sync(0xffffffffu, acc[kk][0], srcB);
            float o2 = __shfl_sync(0xffffffffu, acc[kk][1], srcB);
            float e3 = __shfl_sync(0xffffffffu, acc[kk][2], srcB);
            float o3 = __shfl_sync(0xffffffffu, acc[kk][3], srcB);
            float a0 = odd ? o0 : e0;   // P[r0][8kk+tg]
            float a1 = odd ? o1 : e1;   // P[r1][8kk+tg]
            float a2 = odd ? o2 : e2;   // P[r0][8kk+tg+4]
            float a3 = odd ? o3 : e3;   // P[r1][8kk+tg+4]
            uint32_t ah[4], al[4];
            split2(a0, ah[0], al[0]);
            split2(a1, ah[1], al[1]);
            split2(a2, ah[2], al[2]);
            split2(a3, ah[3], al[3]);
            #pragma unroll
            for (int nt = 0; nt < 8; nt++) {
                const float* vp = Vs + (kk * 8 + tg) * VST + nt * 8 + gr;
                uint32_t bh0, bl0, bh1, bl1;
                split2(vp[0],       bh0, bl0);
                split2(vp[4 * VST], bh1, bl1);
                mma_tf32(oacc[nt], ah[0], ah[1], ah[2], ah[3], bh0, bh1);
                mma_tf32(oacc[nt], ah[0], ah[1], ah[2], ah[3], bl0, bl1);
                mma_tf32(oacc[nt], al[0], al[1], al[2], al[3], bh0, bh1);
            }
        }
    }

    // epilogue
    float* ob = out + (size_t)b * TQ * HD;
    #pragma unroll
    for (int nt = 0; nt < 8; nt++) {
        int c = nt * 8 + 2 * tg;
        *(float2*)(ob + (size_t)r0 * HD + c) = make_float2(oacc[nt][0], oacc[nt][1]);
        *(float2*)(ob + (size_t)r1 * HD + c) = make_float2(oacc[nt][2], oacc[nt][3]);
    }
}

// ============================================================================
extern "C" void kernel_launch(void* const* d_in, const int* in_sizes, int n_in,
                              void* d_out, int out_size)
{
    (void)in_sizes; (void)n_in; (void)out_size;
    const float* x  = (const float*)d_in[0];
    const float* Wq = (const float*)d_in[1];
    const float* Wk = (const float*)d_in[2];
    const float* Wv = (const float*)d_in[3];
    float* out = (float*)d_out;

    cudaFuncSetAttribute(proj_kernel,
                         cudaFuncAttributeMaxDynamicSharedMemorySize, PROJ_SMEM);
    cudaFuncSetAttribute(attn_kernel,
                         cudaFuncAttributeMaxDynamicSharedMemorySize, ATTN_SMEM);

    proj_kernel<<<MTOT / 128, 512, PROJ_SMEM>>>(x, Wq, Wk, Wv);
    attn_kernel<<<NB, 256, ATTN_SMEM>>>(out);
}

// round 5
// speedup vs baseline: 1.8670x; 1.3509x over previous
#include <cuda_runtime.h>
#include <cuda_fp16.h>
#include <cstdint>

// Problem dims
#define NB   512
#define TQ   128
#define CD   384
#define HD   64
#define MTOT (NB*TQ)
#define SCALE 0.4082482904638631f   // 6^-0.5

// ============================================================================
// Device globals (no allocation allowed).
// Q/K/V stored as fp16 hi/lo PAIR WORDS: [row][32 pairs] (pairs along h, even
// element in low half). W pre-split: [n=192][kpair=192].
// ============================================================================
__device__ __align__(16) uint32_t g_qh[MTOT*32];
__device__ __align__(16) uint32_t g_ql[MTOT*32];
__device__ __align__(16) uint32_t g_kh[MTOT*32];
__device__ __align__(16) uint32_t g_kl[MTOT*32];
__device__ __align__(16) uint32_t g_vh[MTOT*32];
__device__ __align__(16) uint32_t g_vl[MTOT*32];
__device__ __align__(16) uint32_t g_whi[192*192];
__device__ __align__(16) uint32_t g_wlo[192*192];

// ---------------- helpers ----------------
__device__ __forceinline__ void mma_f16(float* d, const uint32_t* a,
                                        uint32_t b0, uint32_t b1)
{
    asm("mma.sync.aligned.m16n8k16.row.col.f32.f16.f16.f32 "
        "{%0,%1,%2,%3}, {%4,%5,%6,%7}, {%8,%9}, {%0,%1,%2,%3};"
        : "+f"(d[0]), "+f"(d[1]), "+f"(d[2]), "+f"(d[3])
        : "r"(a[0]), "r"(a[1]), "r"(a[2]), "r"(a[3]), "r"(b0), "r"(b1));
}
// split two floats into fp16 hi pair + fp16 lo (residual) pair
__device__ __forceinline__ void splith(float e0, float e1,
                                       uint32_t& h, uint32_t& l)
{
    __half2 H = __floats2half2_rn(e0, e1);
    float f0 = __low2float(H), f1 = __high2float(H);
    __half2 L = __floats2half2_rn(e0 - f0, e1 - f1);
    h = *(uint32_t*)&H;
    l = *(uint32_t*)&L;
}
__device__ __forceinline__ void cp16(uint32_t s, const void* g) {
    asm volatile("cp.async.cg.shared.global [%0], [%1], 16;" :: "r"(s), "l"(g));
}

// ============================================================================
// Kernel 0: split W -> fp16 hi/lo pair words, layout [n=192][kpair=192]
// ============================================================================
__global__ __launch_bounds__(256) void wsplit_kernel(
    const float* __restrict__ Wq, const float* __restrict__ Wk,
    const float* __restrict__ Wv)
{
    int idx = blockIdx.x * 256 + threadIdx.x;
    if (idx >= 192 * 192) return;
    int n = idx / 192, kp = idx % 192;
    const float* W = (n < 64) ? Wq : (n < 128) ? Wk : Wv;
    int c = n & 63;
    float e0 = W[(size_t)(2 * kp) * HD + c];
    float e1 = W[(size_t)(2 * kp + 1) * HD + c];
    uint32_t h, l;
    splith(e0, e1, h, l);
    g_whi[idx] = h;
    g_wlo[idx] = l;
}

// ============================================================================
// Kernel 1: fused QKV projection, fp16 3-term split on mma.m16n8k16.
// Per CTA: C[64,192] = x[64,384] @ [Wq|Wk|Wv]. BK=16 (one k16 step),
// 256 threads / 8 warps -> 2(m) x 4(n) warp grid, warp tile 32x48.
// Double-buffered smem; A converted in-register at load; B via cp.async.
// smem words: Ah[2][768] Al[2][768] Bh[2][2304] Bl[2][2304] (strides 12).
// ============================================================================
#define PJ_SMEM (12288*4)

__global__ __launch_bounds__(256, 3) void proj_kernel(const float* __restrict__ x)
{
    extern __shared__ uint32_t sw[];
    uint32_t* sAh = sw;             // [2][64*12]
    uint32_t* sAl = sw + 1536;
    uint32_t* sBh = sw + 3072;      // [2][192*12]
    uint32_t* sBl = sw + 7680;
    const uint32_t sb = (uint32_t)__cvta_generic_to_shared(sw);

    const int tid = threadIdx.x, lane = tid & 31, wid = tid >> 5;
    const int mBase = blockIdx.x * 64;
    const int arow = tid >> 2, kq = (tid & 3) * 4, apair = (tid & 3) * 2;
    const float* ag = x + (size_t)(mBase + arow) * CD + kq;

    // B loader: 768 16B-chunks (384 hi + 384 lo), 3 per thread
#define PLOADB(buf, t) do {                                                    \
    _Pragma("unroll")                                                          \
    for (int _j = 0; _j < 3; _j++) {                                           \
        int _id = tid + _j * 256;                                              \
        const uint32_t* _src; uint32_t _dst;                                   \
        if (_id < 384) {                                                       \
            int _r = _id >> 1, _h = _id & 1;                                   \
            _src = g_whi + _r * 192 + (t) * 8 + _h * 4;                        \
            _dst = sb + (3072u + (buf) * 2304u + _r * 12u + _h * 4u) * 4u;     \
        } else {                                                               \
            int _i = _id - 384; int _r = _i >> 1, _h = _i & 1;                 \
            _src = g_wlo + _r * 192 + (t) * 8 + _h * 4;                        \
            _dst = sb + (7680u + (buf) * 2304u + _r * 12u + _h * 4u) * 4u;     \
        }                                                                      \
        cp16(_dst, _src);                                                      \
    }                                                                          \
    asm volatile("cp.async.commit_group;" ::: "memory");                       \
} while (0)

    float4 areg = *(const float4*)ag;
    PLOADB(0, 0);

    const int wm = (wid & 1) * 32, wn = (wid >> 1) * 48;
    const int gr = lane >> 2, tg = lane & 3;

    float acc[2][6][4];
    #pragma unroll
    for (int mt = 0; mt < 2; mt++)
        #pragma unroll
        for (int nt = 0; nt < 6; nt++)
            #pragma unroll
            for (int i = 0; i < 4; i++) acc[mt][nt][i] = 0.f;

    for (int t = 0; t < 24; t++) {
        const int buf = t & 1;
        // store prefetched A tile (split to fp16 hi/lo pairs)
        {
            uint32_t h0, l0, h1, l1;
            splith(areg.x, areg.y, h0, l0);
            splith(areg.z, areg.w, h1, l1);
            *(uint2*)&sAh[buf * 768 + arow * 12 + apair] = make_uint2(h0, h1);
            *(uint2*)&sAl[buf * 768 + arow * 12 + apair] = make_uint2(l0, l1);
        }
        if (t < 23) {
            areg = *(const float4*)(ag + (t + 1) * 16);
            PLOADB(buf ^ 1, t + 1);
            asm volatile("cp.async.wait_group 1;" ::: "memory");
        } else {
            asm volatile("cp.async.wait_group 0;" ::: "memory");
        }
        __syncthreads();

        const uint32_t* Ah = sAh + buf * 768;
        const uint32_t* Al = sAl + buf * 768;
        const uint32_t* Bh = sBh + buf * 2304;
        const uint32_t* Bl = sBl + buf * 2304;

        uint32_t ah[2][4], al[2][4];
        #pragma unroll
        for (int mt = 0; mt < 2; mt++) {
            int r = wm + mt * 16 + gr;
            ah[mt][0] = Ah[r * 12 + tg];       ah[mt][1] = Ah[(r + 8) * 12 + tg];
            ah[mt][2] = Ah[r * 12 + tg + 4];   ah[mt][3] = Ah[(r + 8) * 12 + tg + 4];
            al[mt][0] = Al[r * 12 + tg];       al[mt][1] = Al[(r + 8) * 12 + tg];
            al[mt][2] = Al[r * 12 + tg + 4];   al[mt][3] = Al[(r + 8) * 12 + tg + 4];
        }
        #pragma unroll
        for (int nt = 0; nt < 6; nt++) {
            int n = wn + nt * 8 + gr;
            uint32_t bh0 = Bh[n * 12 + tg], bh1 = Bh[n * 12 + tg + 4];
            uint32_t bl0 = Bl[n * 12 + tg], bl1 = Bl[n * 12 + tg + 4];
            #pragma unroll
            for (int mt = 0; mt < 2; mt++) {
                mma_f16(acc[mt][nt], ah[mt], bh0, bh1);
                mma_f16(acc[mt][nt], ah[mt], bl0, bl1);
                mma_f16(acc[mt][nt], al[mt], bh0, bh1);
            }
        }
    }

    // epilogue: write fp16 hi/lo pair words directly
    #pragma unroll
    for (int nt = 0; nt < 6; nt++) {
        int n = wn + nt * 8;
        uint32_t* Oh = (n < 64) ? g_qh : (n < 128) ? g_kh : g_vh;
        uint32_t* Ol = (n < 64) ? g_ql : (n < 128) ? g_kl : g_vl;
        int pidx = ((n & 63) >> 1) + tg;
        #pragma unroll
        for (int mt = 0; mt < 2; mt++) {
            int r = mBase + wm + mt * 16 + gr;
            uint32_t h, l;
            splith(acc[mt][nt][0], acc[mt][nt][1], h, l);
            Oh[(size_t)r * 32 + pidx] = h;
            Ol[(size_t)r * 32 + pidx] = l;
            splith(acc[mt][nt][2], acc[mt][nt][3], h, l);
            Oh[(size_t)(r + 8) * 32 + pidx] = h;
            Ol[(size_t)(r + 8) * 32 + pidx] = l;
        }
    }
}

// ============================================================================
// Kernel 2: per-batch attention, fp16 3-term mma, S frags feed PV directly.
// smem (words): Qh[128][36] Ql Kh Kl, VtH[64][68] VtL (V transposed).
// 8 warps; warp w owns t-rows [16w,16w+16). Causal tile skip.
// ============================================================================
#define AT_QH 0
#define AT_QL 4608
#define AT_KH 9216
#define AT_KL 13824
#define AT_VH 18432
#define AT_VL 22784
#define ATTN_SMEM (27136*4)

__global__ __launch_bounds__(256, 2) void attn_kernel(float* __restrict__ out)
{
    extern __shared__ uint32_t sw[];
    const uint32_t sb = (uint32_t)__cvta_generic_to_shared(sw);
    const int tid = threadIdx.x, b = blockIdx.x;

    const uint32_t* qh = g_qh + (size_t)b * 4096;
    const uint32_t* ql = g_ql + (size_t)b * 4096;
    const uint32_t* kh = g_kh + (size_t)b * 4096;
    const uint32_t* kl = g_kl + (size_t)b * 4096;
    const uint32_t* vh = g_vh + (size_t)b * 4096;
    const uint32_t* vl = g_vl + (size_t)b * 4096;

    // Q/K straight copy via cp.async (row stride 36 words, 16B chunks)
    #pragma unroll
    for (int i = 0; i < 4; i++) {
        int c = tid + i * 256;
        int row = c >> 3, off = (c & 7) * 4;
        cp16(sb + (AT_QH + row * 36 + off) * 4, qh + row * 32 + off);
        cp16(sb + (AT_QL + row * 36 + off) * 4, ql + row * 32 + off);
        cp16(sb + (AT_KH + row * 36 + off) * 4, kh + row * 32 + off);
        cp16(sb + (AT_KL + row * 36 + off) * 4, kl + row * 32 + off);
    }
    asm volatile("cp.async.commit_group;" ::: "memory");

    // V transpose: [s][hpair] -> Vt[h][s] halves (row stride 68 words)
    {
        __half* VtH = (__half*)(sw + AT_VH);
        __half* VtL = (__half*)(sw + AT_VL);
        #pragma unroll
        for (int i = 0; i < 16; i++) {
            int c = tid + i * 256;          // 0..4095
            int s = c >> 5, h0 = (c & 31) * 2;
            uint32_t wv = vh[c];
            __half2 H = *(__half2*)&wv;
            VtH[h0 * 136 + s]       = __low2half(H);
            VtH[(h0 + 1) * 136 + s] = __high2half(H);
            wv = vl[c];
            H = *(__half2*)&wv;
            VtL[h0 * 136 + s]       = __low2half(H);
            VtL[(h0 + 1) * 136 + s] = __high2half(H);
        }
    }
    asm volatile("cp.async.wait_group 0;" ::: "memory");
    __syncthreads();

    const int w = tid >> 5, lane = tid & 31;
    const int gr = lane >> 2, tg = lane & 3;
    const int t0 = 16 * w;
    const int NT = 2 * w + 2;           // causal: s-tiles 0..NT-1
    const int r0 = t0 + gr, r1 = r0 + 8;

    const uint32_t* Qh = sw + AT_QH;
    const uint32_t* Ql = sw + AT_QL;
    const uint32_t* Kh = sw + AT_KH;
    const uint32_t* Kl = sw + AT_KL;
    const uint32_t* VtH = sw + AT_VH;
    const uint32_t* VtL = sw + AT_VL;

    // ---- QK^T ----
    float acc[16][4];
    #pragma unroll
    for (int nt = 0; nt < 16; nt++)
        #pragma unroll
        for (int i = 0; i < 4; i++) acc[nt][i] = 0.f;

    #pragma unroll
    for (int kk = 0; kk < 4; kk++) {
        uint32_t ah[4], al[4];
        ah[0] = Qh[(t0 + gr) * 36 + 8 * kk + tg];
        ah[1] = Qh[(t0 + gr + 8) * 36 + 8 * kk + tg];
        ah[2] = Qh[(t0 + gr) * 36 + 8 * kk + 4 + tg];
        ah[3] = Qh[(t0 + gr + 8) * 36 + 8 * kk + 4 + tg];
        al[0] = Ql[(t0 + gr) * 36 + 8 * kk + tg];
        al[1] = Ql[(t0 + gr + 8) * 36 + 8 * kk + tg];
        al[2] = Ql[(t0 + gr) * 36 + 8 * kk + 4 + tg];
        al[3] = Ql[(t0 + gr + 8) * 36 + 8 * kk + 4 + tg];
        #pragma unroll
        for (int nt = 0; nt < 16; nt++) {
            if (nt < NT) {
                int s = nt * 8 + gr;
                uint32_t bh0 = Kh[s * 36 + 8 * kk + tg];
                uint32_t bh1 = Kh[s * 36 + 8 * kk + 4 + tg];
                uint32_t bl0 = Kl[s * 36 + 8 * kk + tg];
                uint32_t bl1 = Kl[s * 36 + 8 * kk + 4 + tg];
                mma_f16(acc[nt], ah, bh0, bh1);
                mma_f16(acc[nt], ah, bl0, bl1);
                mma_f16(acc[nt], al, bh0, bh1);
            }
        }
    }

    // ---- softmax in registers ----
    const float NEG = __int_as_float(0xff800000);
    float mx0 = NEG, mx1 = NEG;
    #pragma unroll
    for (int nt = 0; nt < 16; nt++) {
        if (nt < NT) {
            int c = nt * 8 + 2 * tg;
            float v0 = (c     <= r0) ? acc[nt][0] * SCALE : NEG;
            float v1 = (c + 1 <= r0) ? acc[nt][1] * SCALE : NEG;
            float v2 = (c     <= r1) ? acc[nt][2] * SCALE : NEG;
            float v3 = (c + 1 <= r1) ? acc[nt][3] * SCALE : NEG;
            acc[nt][0] = v0; acc[nt][1] = v1; acc[nt][2] = v2; acc[nt][3] = v3;
            mx0 = fmaxf(mx0, fmaxf(v0, v1));
            mx1 = fmaxf(mx1, fmaxf(v2, v3));
        }
    }
    mx0 = fmaxf(mx0, __shfl_xor_sync(0xffffffffu, mx0, 1));
    mx0 = fmaxf(mx0, __shfl_xor_sync(0xffffffffu, mx0, 2));
    mx1 = fmaxf(mx1, __shfl_xor_sync(0xffffffffu, mx1, 1));
    mx1 = fmaxf(mx1, __shfl_xor_sync(0xffffffffu, mx1, 2));

    float s0 = 0.f, s1 = 0.f;
    #pragma unroll
    for (int nt = 0; nt < 16; nt++) {
        if (nt < NT) {
            float p0 = __expf(acc[nt][0] - mx0);
            float p1 = __expf(acc[nt][1] - mx0);
            float p2 = __expf(acc[nt][2] - mx1);
            float p3 = __expf(acc[nt][3] - mx1);
            acc[nt][0] = p0; acc[nt][1] = p1; acc[nt][2] = p2; acc[nt][3] = p3;
            s0 += p0 + p1;  s1 += p2 + p3;
        }
    }
    s0 += __shfl_xor_sync(0xffffffffu, s0, 1);
    s0 += __shfl_xor_sync(0xffffffffu, s0, 2);
    s1 += __shfl_xor_sync(0xffffffffu, s1, 1);
    s1 += __shfl_xor_sync(0xffffffffu, s1, 2);
    const float i0 = 1.0f / s0, i1 = 1.0f / s1;
    #pragma unroll
    for (int nt = 0; nt < 16; nt++) {
        if (nt < NT) {
            acc[nt][0] *= i0; acc[nt][1] *= i0;
            acc[nt][2] *= i1; acc[nt][3] *= i1;
        }
    }

    // ---- PV: P frags come straight from acc (layout match, no shuffles) ----
    float oacc[8][4];
    #pragma unroll
    for (int nt = 0; nt < 8; nt++)
        #pragma unroll
        for (int i = 0; i < 4; i++) oacc[nt][i] = 0.f;

    #pragma unroll
    for (int kk = 0; kk < 8; kk++) {
        if (kk <= w) {
            uint32_t ph[4], pl[4];
            splith(acc[2 * kk][0],     acc[2 * kk][1],     ph[0], pl[0]);
            splith(acc[2 * kk][2],     acc[2 * kk][3],     ph[1], pl[1]);
            splith(acc[2 * kk + 1][0], acc[2 * kk + 1][1], ph[2], pl[2]);
            splith(acc[2 * kk + 1][2], acc[2 * kk + 1][3], ph[3], pl[3]);
            #pragma unroll
            for (int nt = 0; nt < 8; nt++) {
                int h = nt * 8 + gr;
                uint32_t bh0 = VtH[h * 68 + 8 * kk + tg];
                uint32_t bh1 = VtH[h * 68 + 8 * kk + 4 + tg];
                uint32_t bl0 = VtL[h * 68 + 8 * kk + tg];
                uint32_t bl1 = VtL[h * 68 + 8 * kk + 4 + tg];
                mma_f16(oacc[nt], ph, bh0, bh1);
                mma_f16(oacc[nt], ph, bl0, bl1);
                mma_f16(oacc[nt], pl, bh0, bh1);
            }
        }
    }

    // ---- store ----
    float* ob = out + (size_t)b * TQ * HD;
    #pragma unroll
    for (int nt = 0; nt < 8; nt++) {
        int c = nt * 8 + 2 * tg;
        *(float2*)(ob + (size_t)r0 * HD + c) = make_float2(oacc[nt][0], oacc[nt][1]);
        *(float2*)(ob + (size_t)r1 * HD + c) = make_float2(oacc[nt][2], oacc[nt][3]);
    }
}

// ============================================================================
extern "C" void kernel_launch(void* const* d_in, const int* in_sizes, int n_in,
                              void* d_out, int out_size)
{
    (void)in_sizes; (void)n_in; (void)out_size;
    const float* x  = (const float*)d_in[0];
    const float* Wq = (const float*)d_in[1];
    const float* Wk = (const float*)d_in[2];
    const float* Wv = (const float*)d_in[3];
    float* out = (float*)d_out;

    cudaFuncSetAttribute(proj_kernel,
                         cudaFuncAttributeMaxDynamicSharedMemorySize, PJ_SMEM);
    cudaFuncSetAttribute(attn_kernel,
                         cudaFuncAttributeMaxDynamicSharedMemorySize, ATTN_SMEM);

    wsplit_kernel<<<(192 * 192 + 255) / 256, 256>>>(Wq, Wk, Wv);
    proj_kernel<<<MTOT / 64, 256, PJ_SMEM>>>(x);
    attn_kernel<<<NB, 256, ATTN_SMEM>>>(out);
}

// round 6
// speedup vs baseline: 2.3171x; 1.2411x over previous
#include <cuda_runtime.h>
#include <cuda_fp16.h>
#include <cstdint>

// Problem dims
#define NB   512
#define TQ   128
#define CD   384
#define HD   64
#define SCALE 0.4082482904638631f   // 6^-0.5

// W pre-split: fp16 hi/lo pair words, layout [n=192][kpair=192]
__device__ __align__(16) uint32_t g_whi[192*192];
__device__ __align__(16) uint32_t g_wlo[192*192];

// ---------------- helpers ----------------
__device__ __forceinline__ void mma_f16(float* d, const uint32_t* a,
                                        uint32_t b0, uint32_t b1)
{
    asm("mma.sync.aligned.m16n8k16.row.col.f32.f16.f16.f32 "
        "{%0,%1,%2,%3}, {%4,%5,%6,%7}, {%8,%9}, {%0,%1,%2,%3};"
        : "+f"(d[0]), "+f"(d[1]), "+f"(d[2]), "+f"(d[3])
        : "r"(a[0]), "r"(a[1]), "r"(a[2]), "r"(a[3]), "r"(b0), "r"(b1));
}
__device__ __forceinline__ void mma_f16_k8(float* d, uint32_t a0, uint32_t a1,
                                           uint32_t b0)
{
    asm("mma.sync.aligned.m16n8k8.row.col.f32.f16.f16.f32 "
        "{%0,%1,%2,%3}, {%4,%5}, {%6}, {%0,%1,%2,%3};"
        : "+f"(d[0]), "+f"(d[1]), "+f"(d[2]), "+f"(d[3])
        : "r"(a0), "r"(a1), "r"(b0));
}
// split two floats into fp16 hi pair word + fp16 lo (residual) pair word
__device__ __forceinline__ void splith(float e0, float e1,
                                       uint32_t& h, uint32_t& l)
{
    __half2 H = __floats2half2_rn(e0, e1);
    float f0 = __low2float(H), f1 = __high2float(H);
    __half2 L = __floats2half2_rn(e0 - f0, e1 - f1);
    h = *(uint32_t*)&H;
    l = *(uint32_t*)&L;
}
__device__ __forceinline__ void cp16(uint32_t s, const void* g) {
    asm volatile("cp.async.cg.shared.global [%0], [%1], 16;" :: "r"(s), "l"(g));
}

// ============================================================================
// Kernel 0: split W -> fp16 hi/lo pair words, [n=192][kpair=192]
// ============================================================================
__global__ __launch_bounds__(256) void wsplit_kernel(
    const float* __restrict__ Wq, const float* __restrict__ Wk,
    const float* __restrict__ Wv)
{
    int idx = blockIdx.x * 256 + threadIdx.x;
    if (idx >= 192 * 192) return;
    int n = idx / 192, kp = idx % 192;
    const float* W = (n < 64) ? Wq : (n < 128) ? Wk : Wv;
    int c = n & 63;
    float e0 = W[(size_t)(2 * kp) * HD + c];
    float e1 = W[(size_t)(2 * kp + 1) * HD + c];
    uint32_t h, l;
    splith(e0, e1, h, l);
    g_whi[idx] = h;
    g_wlo[idx] = l;
}

// ============================================================================
// Fused kernel: one CTA per batch (512 threads, 16 warps).
// Phase 1 (proj): QKV[128,192] = x_b[128,384] @ [Wq|Wk|Wv], fp16 3-term,
//   BK=16 double-buffered cp.async, warp grid 4(M)x4(N), warp tile 32x48.
//   Epilogue writes Q/K/V hi/lo straight into smem (V transposed).
// Phase 2 (attn): 16 warps; warp pair (tt, half) splits causal s-tiles
//   even/odd. QK on k16, PV on k8 (S frags feed A directly). Partial
//   max/sum/O combined via smem.
// ============================================================================
// smem word offsets
#define PA_H  0          // [2][128*12]
#define PA_L  3072
#define PB_H  6144       // [2][192*12]
#define PB_L  10752
#define AQ_H  15360      // [128][36]
#define AQ_L  19968
#define AK_H  24576
#define AK_L  29184
#define AV_H  33792      // Vt: [64][68]  (half elems: [h][136])
#define AV_L  38144
#define PMX   42496      // float [2][128]
#define PSUM  42752      // float [2][128]
#define OPART 43008      // float [128][66]
#define FU_SMEM ((43008 + 128*66) * 4)   // 205,824 B

__global__ __launch_bounds__(512) void fused_kernel(
    const float* __restrict__ x, float* __restrict__ out)
{
    extern __shared__ uint32_t sw[];
    float* smf = (float*)sw;
    const uint32_t sb = (uint32_t)__cvta_generic_to_shared(sw);
    const int tid = threadIdx.x, b = blockIdx.x;
    const int lane = tid & 31, wid = tid >> 5;
    const int gr = lane >> 2, tg = lane & 3;

    // ------------------------- Phase 1: projection -------------------------
    const int arow = tid >> 2;             // 0..127
    const int kq   = (tid & 3) * 4;        // 0,4,8,12
    const int apair = (tid & 3) * 2;
    const float* ag = x + ((size_t)b * 128 + arow) * CD + kq;

#define PLOADB(buf, t) do {                                                    \
    _Pragma("unroll")                                                          \
    for (int _j = 0; _j < 2; _j++) {                                           \
        int _id = tid + _j * 512;                                              \
        if (_id < 768) {                                                       \
            int _hi = (_id < 384);                                             \
            int _i  = _hi ? _id : _id - 384;                                   \
            int _r = _i >> 1, _hc = _i & 1;                                    \
            const uint32_t* _src = (_hi ? g_whi : g_wlo)                       \
                                   + _r * 192 + (t) * 8 + _hc * 4;             \
            uint32_t _dst = sb + ((_hi ? PB_H : PB_L)                          \
                                  + (buf) * 2304 + _r * 12 + _hc * 4) * 4;     \
            cp16(_dst, _src);                                                  \
        }                                                                      \
    }                                                                          \
    asm volatile("cp.async.commit_group;" ::: "memory");                       \
} while (0)

    const int wm = (wid & 3) * 32;
    const int wn = (wid >> 2) * 48;

    float acc[2][6][4];
    #pragma unroll
    for (int mt = 0; mt < 2; mt++)
        #pragma unroll
        for (int nt = 0; nt < 6; nt++)
            #pragma unroll
            for (int i = 0; i < 4; i++) acc[mt][nt][i] = 0.f;

    float4 areg = *(const float4*)ag;
    PLOADB(0, 0);

    for (int t = 0; t < 24; t++) {
        const int buf = t & 1;
        {   // store A tile (fp16 hi/lo pairs)
            uint32_t h0, l0, h1, l1;
            splith(areg.x, areg.y, h0, l0);
            splith(areg.z, areg.w, h1, l1);
            *(uint2*)&sw[PA_H + buf * 1536 + arow * 12 + apair] = make_uint2(h0, h1);
            *(uint2*)&sw[PA_L + buf * 1536 + arow * 12 + apair] = make_uint2(l0, l1);
        }
        if (t < 23) areg = *(const float4*)(ag + (t + 1) * 16);
        __syncthreads();                       // readers of buf^1 done
        if (t < 23) {
            PLOADB(buf ^ 1, t + 1);
            asm volatile("cp.async.wait_group 1;" ::: "memory");
        } else {
            asm volatile("cp.async.wait_group 0;" ::: "memory");
        }
        __syncthreads();                       // buf's cp.async visible to all

        const uint32_t* Ah = sw + PA_H + buf * 1536;
        const uint32_t* Al = sw + PA_L + buf * 1536;
        const uint32_t* Bh = sw + PB_H + buf * 2304;
        const uint32_t* Bl = sw + PB_L + buf * 2304;

        uint32_t ah[2][4], al[2][4];
        #pragma unroll
        for (int mt = 0; mt < 2; mt++) {
            int r = wm + mt * 16 + gr;
            ah[mt][0] = Ah[r * 12 + tg];       ah[mt][1] = Ah[(r + 8) * 12 + tg];
            ah[mt][2] = Ah[r * 12 + tg + 4];   ah[mt][3] = Ah[(r + 8) * 12 + tg + 4];
            al[mt][0] = Al[r * 12 + tg];       al[mt][1] = Al[(r + 8) * 12 + tg];
            al[mt][2] = Al[r * 12 + tg + 4];   al[mt][3] = Al[(r + 8) * 12 + tg + 4];
        }
        #pragma unroll
        for (int nt = 0; nt < 6; nt++) {
            int n = wn + nt * 8 + gr;
            uint32_t bh0 = Bh[n * 12 + tg], bh1 = Bh[n * 12 + tg + 4];
            uint32_t bl0 = Bl[n * 12 + tg], bl1 = Bl[n * 12 + tg + 4];
            #pragma unroll
            for (int mt = 0; mt < 2; mt++) {
                mma_f16(acc[mt][nt], ah[mt], bh0, bh1);
                mma_f16(acc[mt][nt], ah[mt], bl0, bl1);
                mma_f16(acc[mt][nt], al[mt], bh0, bh1);
            }
        }
    }

    // ---- proj epilogue: write Q/K/V into attn smem (V transposed) ----
    {
        __half* vhh = (__half*)(sw + AV_H);
        __half* vlh = (__half*)(sw + AV_L);
        #pragma unroll
        for (int nt = 0; nt < 6; nt++) {
            int n = wn + nt * 8;
            #pragma unroll
            for (int mt = 0; mt < 2; mt++) {
                int ra = wm + mt * 16 + gr;
                int rb = ra + 8;
                if (n < 128) {
                    int base_h = (n < 64) ? AQ_H : AK_H;
                    int base_l = (n < 64) ? AQ_L : AK_L;
                    int pidx = ((n & 63) >> 1) + tg;
                    uint32_t h, l;
                    splith(acc[mt][nt][0], acc[mt][nt][1], h, l);
                    sw[base_h + ra * 36 + pidx] = h;
                    sw[base_l + ra * 36 + pidx] = l;
                    splith(acc[mt][nt][2], acc[mt][nt][3], h, l);
                    sw[base_h + rb * 36 + pidx] = h;
                    sw[base_l + rb * 36 + pidx] = l;
                } else {
                    int c = (n & 63) + 2 * tg;
                    __half2 H, L;
                    float f0, f1;
                    H = __floats2half2_rn(acc[mt][nt][0], acc[mt][nt][1]);
                    f0 = __low2float(H); f1 = __high2float(H);
                    L = __floats2half2_rn(acc[mt][nt][0] - f0, acc[mt][nt][1] - f1);
                    vhh[c * 136 + ra] = __low2half(H);  vhh[(c + 1) * 136 + ra] = __high2half(H);
                    vlh[c * 136 + ra] = __low2half(L);  vlh[(c + 1) * 136 + ra] = __high2half(L);
                    H = __floats2half2_rn(acc[mt][nt][2], acc[mt][nt][3]);
                    f0 = __low2float(H); f1 = __high2float(H);
                    L = __floats2half2_rn(acc[mt][nt][2] - f0, acc[mt][nt][3] - f1);
                    vhh[c * 136 + rb] = __low2half(H);  vhh[(c + 1) * 136 + rb] = __high2half(H);
                    vlh[c * 136 + rb] = __low2half(L);  vlh[(c + 1) * 136 + rb] = __high2half(L);
                }
            }
        }
    }
    __syncthreads();

    // ------------------------- Phase 2: attention -------------------------
    const int tt = wid >> 1;            // t-tile 0..7 (rows 16tt..16tt+15)
    const int half = wid & 1;           // s-tile parity owned
    const int t0 = 16 * tt;
    const int r0 = t0 + gr, r1 = r0 + 8;

    // QK^T over owned s-tiles st = 2j+half, j<=tt
    float sacc[8][4];
    #pragma unroll
    for (int j = 0; j < 8; j++)
        #pragma unroll
        for (int i = 0; i < 4; i++) sacc[j][i] = 0.f;

    #pragma unroll
    for (int kk = 0; kk < 4; kk++) {
        uint32_t ah[4], al[4];
        ah[0] = sw[AQ_H + r0 * 36 + 8 * kk + tg];
        ah[1] = sw[AQ_H + r1 * 36 + 8 * kk + tg];
        ah[2] = sw[AQ_H + r0 * 36 + 8 * kk + 4 + tg];
        ah[3] = sw[AQ_H + r1 * 36 + 8 * kk + 4 + tg];
        al[0] = sw[AQ_L + r0 * 36 + 8 * kk + tg];
        al[1] = sw[AQ_L + r1 * 36 + 8 * kk + tg];
        al[2] = sw[AQ_L + r0 * 36 + 8 * kk + 4 + tg];
        al[3] = sw[AQ_L + r1 * 36 + 8 * kk + 4 + tg];
        #pragma unroll
        for (int j = 0; j < 8; j++) {
            if (j <= tt) {
                int s = (2 * j + half) * 8 + gr;
                uint32_t bh0 = sw[AK_H + s * 36 + 8 * kk + tg];
                uint32_t bh1 = sw[AK_H + s * 36 + 8 * kk + 4 + tg];
                uint32_t bl0 = sw[AK_L + s * 36 + 8 * kk + tg];
                uint32_t bl1 = sw[AK_L + s * 36 + 8 * kk + 4 + tg];
                mma_f16(sacc[j], ah, bh0, bh1);
                mma_f16(sacc[j], ah, bl0, bl1);
                mma_f16(sacc[j], al, bh0, bh1);
            }
        }
    }

    // masked scale + partial max
    const float NEG = __int_as_float(0xff800000);
    float mx0 = NEG, mx1 = NEG;
    #pragma unroll
    for (int j = 0; j < 8; j++) {
        if (j <= tt) {
            int c = (2 * j + half) * 8 + 2 * tg;
            float v0 = (c     <= r0) ? sacc[j][0] * SCALE : NEG;
            float v1 = (c + 1 <= r0) ? sacc[j][1] * SCALE : NEG;
            float v2 = (c     <= r1) ? sacc[j][2] * SCALE : NEG;
            float v3 = (c + 1 <= r1) ? sacc[j][3] * SCALE : NEG;
            sacc[j][0] = v0; sacc[j][1] = v1; sacc[j][2] = v2; sacc[j][3] = v3;
            mx0 = fmaxf(mx0, fmaxf(v0, v1));
            mx1 = fmaxf(mx1, fmaxf(v2, v3));
        }
    }
    mx0 = fmaxf(mx0, __shfl_xor_sync(0xffffffffu, mx0, 1));
    mx0 = fmaxf(mx0, __shfl_xor_sync(0xffffffffu, mx0, 2));
    mx1 = fmaxf(mx1, __shfl_xor_sync(0xffffffffu, mx1, 1));
    mx1 = fmaxf(mx1, __shfl_xor_sync(0xffffffffu, mx1, 2));
    if (tg == 0) {
        smf[PMX + half * 128 + r0] = mx0;
        smf[PMX + half * 128 + r1] = mx1;
    }
    __syncthreads();
    mx0 = fmaxf(smf[PMX + r0], smf[PMX + 128 + r0]);
    mx1 = fmaxf(smf[PMX + r1], smf[PMX + 128 + r1]);

    float s0 = 0.f, s1 = 0.f;
    #pragma unroll
    for (int j = 0; j < 8; j++) {
        if (j <= tt) {
            float p0 = __expf(sacc[j][0] - mx0);
            float p1 = __expf(sacc[j][1] - mx0);
            float p2 = __expf(sacc[j][2] - mx1);
            float p3 = __expf(sacc[j][3] - mx1);
            sacc[j][0] = p0; sacc[j][1] = p1; sacc[j][2] = p2; sacc[j][3] = p3;
            s0 += p0 + p1;  s1 += p2 + p3;
        }
    }
    s0 += __shfl_xor_sync(0xffffffffu, s0, 1);
    s0 += __shfl_xor_sync(0xffffffffu, s0, 2);
    s1 += __shfl_xor_sync(0xffffffffu, s1, 1);
    s1 += __shfl_xor_sync(0xffffffffu, s1, 2);
    if (tg == 0) {
        smf[PSUM + half * 128 + r0] = s0;
        smf[PSUM + half * 128 + r1] = s1;
    }
    __syncthreads();
    const float i0 = 1.0f / (smf[PSUM + r0] + smf[PSUM + 128 + r0]);
    const float i1 = 1.0f / (smf[PSUM + r1] + smf[PSUM + 128 + r1]);
    #pragma unroll
    for (int j = 0; j < 8; j++) {
        if (j <= tt) {
            sacc[j][0] *= i0; sacc[j][1] *= i0;
            sacc[j][2] *= i1; sacc[j][3] *= i1;
        }
    }

    // PV on k8: S frags feed A directly, B from transposed V
    float oacc[8][4];
    #pragma unroll
    for (int ht = 0; ht < 8; ht++)
        #pragma unroll
        for (int i = 0; i < 4; i++) oacc[ht][i] = 0.f;

    #pragma unroll
    for (int j = 0; j < 8; j++) {
        if (j <= tt) {
            int st = 2 * j + half;
            uint32_t p0h, p0l, p1h, p1l;
            splith(sacc[j][0], sacc[j][1], p0h, p0l);
            splith(sacc[j][2], sacc[j][3], p1h, p1l);
            #pragma unroll
            for (int ht = 0; ht < 8; ht++) {
                int h = ht * 8 + gr;
                uint32_t bh = sw[AV_H + h * 68 + 4 * st + tg];
                uint32_t bl = sw[AV_L + h * 68 + 4 * st + tg];
                mma_f16_k8(oacc[ht], p0h, p1h, bh);
                mma_f16_k8(oacc[ht], p0h, p1h, bl);
                mma_f16_k8(oacc[ht], p0l, p1l, bh);
            }
        }
    }

    // combine halves and store
    if (half) {
        #pragma unroll
        for (int ht = 0; ht < 8; ht++) {
            int c = ht * 8 + 2 * tg;
            *(float2*)&smf[OPART + r0 * 66 + c] = make_float2(oacc[ht][0], oacc[ht][1]);
            *(float2*)&smf[OPART + r1 * 66 + c] = make_float2(oacc[ht][2], oacc[ht][3]);
        }
    }
    __syncthreads();
    if (!half) {
        float* ob = out + (size_t)b * TQ * HD;
        #pragma unroll
        for (int ht = 0; ht < 8; ht++) {
            int c = ht * 8 + 2 * tg;
            float2 q0 = *(float2*)&smf[OPART + r0 * 66 + c];
            float2 q1 = *(float2*)&smf[OPART + r1 * 66 + c];
            *(float2*)(ob + (size_t)r0 * HD + c) =
                make_float2(oacc[ht][0] + q0.x, oacc[ht][1] + q0.y);
            *(float2*)(ob + (size_t)r1 * HD + c) =
                make_float2(oacc[ht][2] + q1.x, oacc[ht][3] + q1.y);
        }
    }
}

// ============================================================================
extern "C" void kernel_launch(void* const* d_in, const int* in_sizes, int n_in,
                              void* d_out, int out_size)
{
    (void)in_sizes; (void)n_in; (void)out_size;
    const float* x  = (const float*)d_in[0];
    const float* Wq = (const float*)d_in[1];
    const float* Wk = (const float*)d_in[2];
    const float* Wv = (const float*)d_in[3];
    float* out = (float*)d_out;

    cudaFuncSetAttribute(fused_kernel,
                         cudaFuncAttributeMaxDynamicSharedMemorySize, FU_SMEM);

    wsplit_kernel<<<(192 * 192 + 255) / 256, 256>>>(Wq, Wk, Wv);
    fused_kernel<<<NB, 512, FU_SMEM>>>(x, out);
}

// round 7
// speedup vs baseline: 2.7765x; 1.1983x over previous
#include <cuda_runtime.h>
#include <cuda_fp16.h>
#include <cstdint>

// Problem dims
#define NB   512
#define TQ   128
#define CD   384
#define HD   64
#define SCALE 0.4082482904638631f   // 6^-0.5

// W pre-split: fp16 hi/lo pair words, layout [n=192][kpair=192]
__device__ __align__(16) uint32_t g_whi[192*192];
__device__ __align__(16) uint32_t g_wlo[192*192];

// ---------------- helpers ----------------
__device__ __forceinline__ void mma_f16(float* d, const uint32_t* a,
                                        uint32_t b0, uint32_t b1)
{
    asm("mma.sync.aligned.m16n8k16.row.col.f32.f16.f16.f32 "
        "{%0,%1,%2,%3}, {%4,%5,%6,%7}, {%8,%9}, {%0,%1,%2,%3};"
        : "+f"(d[0]), "+f"(d[1]), "+f"(d[2]), "+f"(d[3])
        : "r"(a[0]), "r"(a[1]), "r"(a[2]), "r"(a[3]), "r"(b0), "r"(b1));
}
__device__ __forceinline__ void mma_f16_k8(float* d, uint32_t a0, uint32_t a1,
                                           uint32_t b0)
{
    asm("mma.sync.aligned.m16n8k8.row.col.f32.f16.f16.f32 "
        "{%0,%1,%2,%3}, {%4,%5}, {%6}, {%0,%1,%2,%3};"
        : "+f"(d[0]), "+f"(d[1]), "+f"(d[2]), "+f"(d[3])
        : "r"(a0), "r"(a1), "r"(b0));
}
#define LDM4(r, a) \
    asm volatile("ldmatrix.sync.aligned.m8n8.x4.shared.b16 {%0,%1,%2,%3}, [%4];" \
        : "=r"((r)[0]), "=r"((r)[1]), "=r"((r)[2]), "=r"((r)[3]) : "r"(a))

__device__ __forceinline__ void splith(float e0, float e1,
                                       uint32_t& h, uint32_t& l)
{
    __half2 H = __floats2half2_rn(e0, e1);
    float f0 = __low2float(H), f1 = __high2float(H);
    __half2 L = __floats2half2_rn(e0 - f0, e1 - f1);
    h = *(uint32_t*)&H;
    l = *(uint32_t*)&L;
}
__device__ __forceinline__ void cp16(uint32_t s, const void* g) {
    asm volatile("cp.async.cg.shared.global [%0], [%1], 16;" :: "r"(s), "l"(g));
}

// ============================================================================
// Kernel 0: split W -> fp16 hi/lo pair words, [n=192][kpair=192]
// ============================================================================
__global__ __launch_bounds__(256) void wsplit_kernel(
    const float* __restrict__ Wq, const float* __restrict__ Wk,
    const float* __restrict__ Wv)
{
    int idx = blockIdx.x * 256 + threadIdx.x;
    if (idx >= 192 * 192) return;
    int n = idx / 192, kp = idx % 192;
    const float* W = (n < 64) ? Wq : (n < 128) ? Wk : Wv;
    int c = n & 63;
    float e0 = W[(size_t)(2 * kp) * HD + c];
    float e1 = W[(size_t)(2 * kp + 1) * HD + c];
    uint32_t h, l;
    splith(e0, e1, h, l);
    g_whi[idx] = h;
    g_wlo[idx] = l;
}

// ============================================================================
// Fused kernel: one CTA per batch (512 threads, 16 warps).
// Phase 1 (proj): BK=32, single-sync double-buffered pipeline, ldmatrix frags.
// Phase 2 (attn): as R6 (warp pair splits causal s-tiles even/odd).
// ============================================================================
// smem word offsets
#define PA_H  0          // [2][128*20]
#define PA_L  5120
#define PB_H  10240      // [2][192*20]
#define PB_L  17920
#define AQ_H  25600      // [128][36]
#define AQ_L  30208
#define AK_H  34816
#define AK_L  39424
#define AV_H  44032      // Vt: [64][68]  (half elems: [h][136])
#define AV_L  48384
// overlaid on dead proj buffers:
#define PMX   0          // float [2][128]
#define PSUM  256        // float [2][128]
#define OPART 512        // float [128][66]
#define FU_SMEM (52736 * 4)   // 210,944 B

__global__ __launch_bounds__(512) void fused_kernel(
    const float* __restrict__ x, float* __restrict__ out)
{
    extern __shared__ uint32_t sw[];
    float* smf = (float*)sw;
    const uint32_t sb = (uint32_t)__cvta_generic_to_shared(sw);
    const int tid = threadIdx.x, b = blockIdx.x;
    const int lane = tid & 31, wid = tid >> 5;
    const int gr = lane >> 2, tg = lane & 3;

    // ------------------------- Phase 1: projection -------------------------
    const int arow = tid >> 2;             // 0..127
    const int kw   = (tid & 3) * 4;        // pair-word offset within 16
    const float* ag = x + ((size_t)b * 128 + arow) * CD + (tid & 3) * 8;

    // B loader precompute: 1536 chunks, 3 per thread
    int bl_n[3], bl_ch[3];
    const uint32_t* bl_src[3];
    uint32_t bl_dstw[3];
    #pragma unroll
    for (int j = 0; j < 3; j++) {
        int id = tid + j * 512;
        int hi = (id < 768);
        int i = hi ? id : id - 768;
        bl_n[j] = i >> 2; bl_ch[j] = i & 3;
        bl_src[j] = (hi ? g_whi : g_wlo) + bl_n[j] * 192 + bl_ch[j] * 4;
        bl_dstw[j] = (hi ? PB_H : PB_L) + bl_n[j] * 20 + bl_ch[j] * 4;
    }
#define PLOADB(buf, t) do {                                                    \
    _Pragma("unroll")                                                          \
    for (int _j = 0; _j < 3; _j++)                                             \
        cp16(sb + (bl_dstw[_j] + (buf) * 3840) * 4, bl_src[_j] + (t) * 16);    \
    asm volatile("cp.async.commit_group;" ::: "memory");                       \
} while (0)

#define STOREA(buf, r0v, r1v) do {                                             \
    uint32_t _h0,_l0,_h1,_l1,_h2,_l2,_h3,_l3;                                  \
    splith((r0v).x, (r0v).y, _h0, _l0); splith((r0v).z, (r0v).w, _h1, _l1);    \
    splith((r1v).x, (r1v).y, _h2, _l2); splith((r1v).z, (r1v).w, _h3, _l3);    \
    uint32_t* _pH = sw + PA_H + (buf) * 2560 + arow * 20 + kw;                 \
    uint32_t* _pL = sw + PA_L + (buf) * 2560 + arow * 20 + kw;                 \
    *(uint2*)_pH = make_uint2(_h0, _h1); *(uint2*)(_pH + 2) = make_uint2(_h2, _h3); \
    *(uint2*)_pL = make_uint2(_l0, _l1); *(uint2*)(_pL + 2) = make_uint2(_l2, _l3); \
} while (0)

    const int wm = (wid & 3) * 32;
    const int wn = (wid >> 2) * 48;

    // ldmatrix per-lane byte offsets (within region)
    const int a_r = (lane & 7) + ((lane >> 3) & 1) * 8;
    const int a_c = ((lane >> 4) & 1) * 4;
    const uint32_t aoff0 = ((wm + a_r) * 20 + a_c) * 4;
    const uint32_t aoff1 = ((wm + 16 + a_r) * 20 + a_c) * 4;
    const int b_r = lane & 7;
    const int b_half = (lane >> 3) & 1;
    const int b_nt = (lane >> 4) & 1;
    uint32_t boff[3];
    #pragma unroll
    for (int p = 0; p < 3; p++)
        boff[p] = ((wn + (2 * p + b_nt) * 8 + b_r) * 20 + b_half * 4) * 4;

    float acc[2][6][4];
    #pragma unroll
    for (int mt = 0; mt < 2; mt++)
        #pragma unroll
        for (int nt = 0; nt < 6; nt++)
            #pragma unroll
            for (int i = 0; i < 4; i++) acc[mt][nt][i] = 0.f;

    // prologue
    float4 ar0 = *(const float4*)ag;
    float4 ar1 = *(const float4*)(ag + 4);
    STOREA(0, ar0, ar1);
    PLOADB(0, 0);
    ar0 = *(const float4*)(ag + 32);
    ar1 = *(const float4*)(ag + 36);

    for (int t = 0; t < 12; t++) {
        const int buf = t & 1;
        asm volatile("cp.async.wait_group 0;" ::: "memory");
        __syncthreads();
        if (t < 11) {
            STOREA(buf ^ 1, ar0, ar1);
            PLOADB(buf ^ 1, t + 1);
            if (t < 10) {
                ar0 = *(const float4*)(ag + (t + 2) * 32);
                ar1 = *(const float4*)(ag + (t + 2) * 32 + 4);
            }
        }
        const uint32_t aBH = sb + (PA_H + buf * 2560) * 4;
        const uint32_t aBL = sb + (PA_L + buf * 2560) * 4;
        const uint32_t bBH = sb + (PB_H + buf * 3840) * 4;
        const uint32_t bBL = sb + (PB_L + buf * 3840) * 4;
        #pragma unroll
        for (int kk = 0; kk < 2; kk++) {
            uint32_t AH0[4], AH1[4], AL0[4], AL1[4];
            LDM4(AH0, aBH + aoff0 + kk * 32);
            LDM4(AH1, aBH + aoff1 + kk * 32);
            LDM4(AL0, aBL + aoff0 + kk * 32);
            LDM4(AL1, aBL + aoff1 + kk * 32);
            #pragma unroll
            for (int p = 0; p < 3; p++) {
                uint32_t BH[4], BL[4];
                LDM4(BH, bBH + boff[p] + kk * 32);
                LDM4(BL, bBL + boff[p] + kk * 32);
                mma_f16(acc[0][2*p],   AH0, BH[0], BH[1]);
                mma_f16(acc[0][2*p],   AH0, BL[0], BL[1]);
                mma_f16(acc[0][2*p],   AL0, BH[0], BH[1]);
                mma_f16(acc[1][2*p],   AH1, BH[0], BH[1]);
                mma_f16(acc[1][2*p],   AH1, BL[0], BL[1]);
                mma_f16(acc[1][2*p],   AL1, BH[0], BH[1]);
                mma_f16(acc[0][2*p+1], AH0, BH[2], BH[3]);
                mma_f16(acc[0][2*p+1], AH0, BL[2], BL[3]);
                mma_f16(acc[0][2*p+1], AL0, BH[2], BH[3]);
                mma_f16(acc[1][2*p+1], AH1, BH[2], BH[3]);
                mma_f16(acc[1][2*p+1], AH1, BL[2], BL[3]);
                mma_f16(acc[1][2*p+1], AL1, BH[2], BH[3]);
            }
        }
    }

    // ---- proj epilogue: write Q/K/V into attn smem (V transposed) ----
    {
        __half* vhh = (__half*)(sw + AV_H);
        __half* vlh = (__half*)(sw + AV_L);
        #pragma unroll
        for (int nt = 0; nt < 6; nt++) {
            int n = wn + nt * 8;
            #pragma unroll
            for (int mt = 0; mt < 2; mt++) {
                int ra = wm + mt * 16 + gr;
                int rb = ra + 8;
                if (n < 128) {
                    int base_h = (n < 64) ? AQ_H : AK_H;
                    int base_l = (n < 64) ? AQ_L : AK_L;
                    int pidx = ((n & 63) >> 1) + tg;
                    uint32_t h, l;
                    splith(acc[mt][nt][0], acc[mt][nt][1], h, l);
                    sw[base_h + ra * 36 + pidx] = h;
                    sw[base_l + ra * 36 + pidx] = l;
                    splith(acc[mt][nt][2], acc[mt][nt][3], h, l);
                    sw[base_h + rb * 36 + pidx] = h;
                    sw[base_l + rb * 36 + pidx] = l;
                } else {
                    int c = (n & 63) + 2 * tg;
                    __half2 H, L;
                    float f0, f1;
                    H = __floats2half2_rn(acc[mt][nt][0], acc[mt][nt][1]);
                    f0 = __low2float(H); f1 = __high2float(H);
                    L = __floats2half2_rn(acc[mt][nt][0] - f0, acc[mt][nt][1] - f1);
                    vhh[c * 136 + ra] = __low2half(H);  vhh[(c + 1) * 136 + ra] = __high2half(H);
                    vlh[c * 136 + ra] = __low2half(L);  vlh[(c + 1) * 136 + ra] = __high2half(L);
                    H = __floats2half2_rn(acc[mt][nt][2], acc[mt][nt][3]);
                    f0 = __low2float(H); f1 = __high2float(H);
                    L = __floats2half2_rn(acc[mt][nt][2] - f0, acc[mt][nt][3] - f1);
                    vhh[c * 136 + rb] = __low2half(H);  vhh[(c + 1) * 136 + rb] = __high2half(H);
                    vlh[c * 136 + rb] = __low2half(L);  vlh[(c + 1) * 136 + rb] = __high2half(L);
                }
            }
        }
    }
    __syncthreads();

    // ------------------------- Phase 2: attention -------------------------
    const int tt = wid >> 1;
    const int half = wid & 1;
    const int t0 = 16 * tt;
    const int r0 = t0 + gr, r1 = r0 + 8;

    float sacc[8][4];
    #pragma unroll
    for (int j = 0; j < 8; j++)
        #pragma unroll
        for (int i = 0; i < 4; i++) sacc[j][i] = 0.f;

    #pragma unroll
    for (int kk = 0; kk < 4; kk++) {
        uint32_t ah[4], al[4];
        ah[0] = sw[AQ_H + r0 * 36 + 8 * kk + tg];
        ah[1] = sw[AQ_H + r1 * 36 + 8 * kk + tg];
        ah[2] = sw[AQ_H + r0 * 36 + 8 * kk + 4 + tg];
        ah[3] = sw[AQ_H + r1 * 36 + 8 * kk + 4 + tg];
        al[0] = sw[AQ_L + r0 * 36 + 8 * kk + tg];
        al[1] = sw[AQ_L + r1 * 36 + 8 * kk + tg];
        al[2] = sw[AQ_L + r0 * 36 + 8 * kk + 4 + tg];
        al[3] = sw[AQ_L + r1 * 36 + 8 * kk + 4 + tg];
        #pragma unroll
        for (int j = 0; j < 8; j++) {
            if (j <= tt) {
                int s = (2 * j + half) * 8 + gr;
                uint32_t bh0 = sw[AK_H + s * 36 + 8 * kk + tg];
                uint32_t bh1 = sw[AK_H + s * 36 + 8 * kk + 4 + tg];
                uint32_t bl0 = sw[AK_L + s * 36 + 8 * kk + tg];
                uint32_t bl1 = sw[AK_L + s * 36 + 8 * kk + 4 + tg];
                mma_f16(sacc[j], ah, bh0, bh1);
                mma_f16(sacc[j], ah, bl0, bl1);
                mma_f16(sacc[j], al, bh0, bh1);
            }
        }
    }

    const float NEG = __int_as_float(0xff800000);
    float mx0 = NEG, mx1 = NEG;
    #pragma unroll
    for (int j = 0; j < 8; j++) {
        if (j <= tt) {
            int c = (2 * j + half) * 8 + 2 * tg;
            float v0 = (c     <= r0) ? sacc[j][0] * SCALE : NEG;
            float v1 = (c + 1 <= r0) ? sacc[j][1] * SCALE : NEG;
            float v2 = (c     <= r1) ? sacc[j][2] * SCALE : NEG;
            float v3 = (c + 1 <= r1) ? sacc[j][3] * SCALE : NEG;
            sacc[j][0] = v0; sacc[j][1] = v1; sacc[j][2] = v2; sacc[j][3] = v3;
            mx0 = fmaxf(mx0, fmaxf(v0, v1));
            mx1 = fmaxf(mx1, fmaxf(v2, v3));
        }
    }
    mx0 = fmaxf(mx0, __shfl_xor_sync(0xffffffffu, mx0, 1));
    mx0 = fmaxf(mx0, __shfl_xor_sync(0xffffffffu, mx0, 2));
    mx1 = fmaxf(mx1, __shfl_xor_sync(0xffffffffu, mx1, 1));
    mx1 = fmaxf(mx1, __shfl_xor_sync(0xffffffffu, mx1, 2));
    if (tg == 0) {
        smf[PMX + half * 128 + r0] = mx0;
        smf[PMX + half * 128 + r1] = mx1;
    }
    __syncthreads();
    mx0 = fmaxf(smf[PMX + r0], smf[PMX + 128 + r0]);
    mx1 = fmaxf(smf[PMX + r1], smf[PMX + 128 + r1]);

    float s0 = 0.f, s1 = 0.f;
    #pragma unroll
    for (int j = 0; j < 8; j++) {
        if (j <= tt) {
            float p0 = __expf(sacc[j][0] - mx0);
            float p1 = __expf(sacc[j][1] - mx0);
            float p2 = __expf(sacc[j][2] - mx1);
            float p3 = __expf(sacc[j][3] - mx1);
            sacc[j][0] = p0; sacc[j][1] = p1; sacc[j][2] = p2; sacc[j][3] = p3;
            s0 += p0 + p1;  s1 += p2 + p3;
        }
    }
    s0 += __shfl_xor_sync(0xffffffffu, s0, 1);
    s0 += __shfl_xor_sync(0xffffffffu, s0, 2);
    s1 += __shfl_xor_sync(0xffffffffu, s1, 1);
    s1 += __shfl_xor_sync(0xffffffffu, s1, 2);
    if (tg == 0) {
        smf[PSUM + half * 128 + r0] = s0;
        smf[PSUM + half * 128 + r1] = s1;
    }
    __syncthreads();
    const float i0 = 1.0f / (smf[PSUM + r0] + smf[PSUM + 128 + r0]);
    const float i1 = 1.0f / (smf[PSUM + r1] + smf[PSUM + 128 + r1]);
    #pragma unroll
    for (int j = 0; j < 8; j++) {
        if (j <= tt) {
            sacc[j][0] *= i0; sacc[j][1] *= i0;
            sacc[j][2] *= i1; sacc[j][3] *= i1;
        }
    }

    float oacc[8][4];
    #pragma unroll
    for (int ht = 0; ht < 8; ht++)
        #pragma unroll
        for (int i = 0; i < 4; i++) oacc[ht][i] = 0.f;

    #pragma unroll
    for (int j = 0; j < 8; j++) {
        if (j <= tt) {
            int st = 2 * j + half;
            uint32_t p0h, p0l, p1h, p1l;
            splith(sacc[j][0], sacc[j][1], p0h, p0l);
            splith(sacc[j][2], sacc[j][3], p1h, p1l);
            #pragma unroll
            for (int ht = 0; ht < 8; ht++) {
                int h = ht * 8 + gr;
                uint32_t bh = sw[AV_H + h * 68 + 4 * st + tg];
                uint32_t bl = sw[AV_L + h * 68 + 4 * st + tg];
                mma_f16_k8(oacc[ht], p0h, p1h, bh);
                mma_f16_k8(oacc[ht], p0h, p1h, bl);
                mma_f16_k8(oacc[ht], p0l, p1l, bh);
            }
        }
    }

    if (half) {
        #pragma unroll
        for (int ht = 0; ht < 8; ht++) {
            int c = ht * 8 + 2 * tg;
            *(float2*)&smf[OPART + r0 * 66 + c] = make_float2(oacc[ht][0], oacc[ht][1]);
            *(float2*)&smf[OPART + r1 * 66 + c] = make_float2(oacc[ht][2], oacc[ht][3]);
        }
    }
    __syncthreads();
    if (!half) {
        float* ob = out + (size_t)b * TQ * HD;
        #pragma unroll
        for (int ht = 0; ht < 8; ht++) {
            int c = ht * 8 + 2 * tg;
            float2 q0 = *(float2*)&smf[OPART + r0 * 66 + c];
            float2 q1 = *(float2*)&smf[OPART + r1 * 66 + c];
            *(float2*)(ob + (size_t)r0 * HD + c) =
                make_float2(oacc[ht][0] + q0.x, oacc[ht][1] + q0.y);
            *(float2*)(ob + (size_t)r1 * HD + c) =
                make_float2(oacc[ht][2] + q1.x, oacc[ht][3] + q1.y);
        }
    }
}

// ============================================================================
extern "C" void kernel_launch(void* const* d_in, const int* in_sizes, int n_in,
                              void* d_out, int out_size)
{
    (void)in_sizes; (void)n_in; (void)out_size;
    const float* x  = (const float*)d_in[0];
    const float* Wq = (const float*)d_in[1];
    const float* Wk = (const float*)d_in[2];
    const float* Wv = (const float*)d_in[3];
    float* out = (float*)d_out;

    cudaFuncSetAttribute(fused_kernel,
                         cudaFuncAttributeMaxDynamicSharedMemorySize, FU_SMEM);

    wsplit_kernel<<<(192 * 192 + 255) / 256, 256>>>(Wq, Wk, Wv);
    fused_kernel<<<NB, 512, FU_SMEM>>>(x, out);
}

// round 8
// speedup vs baseline: 2.9125x; 1.0490x over previous
#include <cuda_runtime.h>
#include <cuda_fp16.h>
#include <cstdint>

// Problem dims
#define NB   512
#define TQ   128
#define CD   384
#define HD   64
#define SCALE 0.4082482904638631f   // 6^-0.5

// W pre-split: fp16 hi/lo pair words, layout [n=192][kpair=192]
__device__ __align__(16) uint32_t g_whi[192*192];
__device__ __align__(16) uint32_t g_wlo[192*192];

// ---------------- helpers ----------------
__device__ __forceinline__ void mma_f16(float* d, const uint32_t* a,
                                        uint32_t b0, uint32_t b1)
{
    asm("mma.sync.aligned.m16n8k16.row.col.f32.f16.f16.f32 "
        "{%0,%1,%2,%3}, {%4,%5,%6,%7}, {%8,%9}, {%0,%1,%2,%3};"
        : "+f"(d[0]), "+f"(d[1]), "+f"(d[2]), "+f"(d[3])
        : "r"(a[0]), "r"(a[1]), "r"(a[2]), "r"(a[3]), "r"(b0), "r"(b1));
}
__device__ __forceinline__ void mma_f16_k8(float* d, uint32_t a0, uint32_t a1,
                                           uint32_t b0)
{
    asm("mma.sync.aligned.m16n8k8.row.col.f32.f16.f16.f32 "
        "{%0,%1,%2,%3}, {%4,%5}, {%6}, {%0,%1,%2,%3};"
        : "+f"(d[0]), "+f"(d[1]), "+f"(d[2]), "+f"(d[3])
        : "r"(a0), "r"(a1), "r"(b0));
}
#define LDM4(r, a) \
    asm volatile("ldmatrix.sync.aligned.m8n8.x4.shared.b16 {%0,%1,%2,%3}, [%4];" \
        : "=r"((r)[0]), "=r"((r)[1]), "=r"((r)[2]), "=r"((r)[3]) : "r"(a))

__device__ __forceinline__ void splith(float e0, float e1,
                                       uint32_t& h, uint32_t& l)
{
    __half2 H = __floats2half2_rn(e0, e1);
    float f0 = __low2float(H), f1 = __high2float(H);
    __half2 L = __floats2half2_rn(e0 - f0, e1 - f1);
    h = *(uint32_t*)&H;
    l = *(uint32_t*)&L;
}
__device__ __forceinline__ void cp16(uint32_t s, const void* g) {
    asm volatile("cp.async.cg.shared.global [%0], [%1], 16;" :: "r"(s), "l"(g));
}

// ============================================================================
// Kernel 0: split W -> fp16 hi/lo pair words, [n=192][kpair=192]
// Mapping chosen so GLOBAL READS coalesce (writes scatter, fire-and-forget).
// ============================================================================
__global__ __launch_bounds__(256) void wsplit_kernel(
    const float* __restrict__ Wq, const float* __restrict__ Wk,
    const float* __restrict__ Wv)
{
    int idx = blockIdx.x * 256 + threadIdx.x;
    if (idx >= 192 * 192) return;
    int kp = idx / 192, n = idx % 192;        // n fastest -> coalesced reads
    const float* W = (n < 64) ? Wq : (n < 128) ? Wk : Wv;
    int c = n & 63;
    float e0 = W[(size_t)(2 * kp) * HD + c];
    float e1 = W[(size_t)(2 * kp + 1) * HD + c];
    uint32_t h, l;
    splith(e0, e1, h, l);
    g_whi[n * 192 + kp] = h;
    g_wlo[n * 192 + kp] = l;
}

// ============================================================================
// Fused kernel: one CTA per batch (512 threads, 16 warps).
// ============================================================================
// smem word offsets
#define PA_H  0          // [2][128*20]
#define PA_L  5120
#define PB_H  10240      // [2][192*20]
#define PB_L  17920
#define AQ_H  25600      // [128][36]
#define AQ_L  30208
#define AK_H  34816
#define AK_L  39424
#define AV_H  44032      // Vt: [64][68]  (half elems: [h][136])
#define AV_L  48384
// overlaid on dead proj buffers:
#define PMX   0          // float [2][128]
#define PSUM  256        // float [2][128]
#define OPART 512        // float [128][66]
#define FU_SMEM (52736 * 4)   // 210,944 B

__global__ __launch_bounds__(512) void fused_kernel(
    const float* __restrict__ x, float* __restrict__ out)
{
    extern __shared__ uint32_t sw[];
    float* smf = (float*)sw;
    const uint32_t sb = (uint32_t)__cvta_generic_to_shared(sw);
    const int tid = threadIdx.x, b = blockIdx.x;
    const int lane = tid & 31, wid = tid >> 5;
    const int gr = lane >> 2, tg = lane & 3;

    // ------------------------- Phase 1: projection -------------------------
    const int arow = tid >> 2;
    const int kw   = (tid & 3) * 4;
    const float* ag = x + ((size_t)b * 128 + arow) * CD + (tid & 3) * 8;

    const uint32_t* bl_src[3];
    uint32_t bl_dstw[3];
    #pragma unroll
    for (int j = 0; j < 3; j++) {
        int id = tid + j * 512;
        int hi = (id < 768);
        int i = hi ? id : id - 768;
        int bn = i >> 2, bch = i & 3;
        bl_src[j] = (hi ? g_whi : g_wlo) + bn * 192 + bch * 4;
        bl_dstw[j] = (hi ? PB_H : PB_L) + bn * 20 + bch * 4;
    }
#define PLOADB(buf, t) do {                                                    \
    _Pragma("unroll")                                                          \
    for (int _j = 0; _j < 3; _j++)                                             \
        cp16(sb + (bl_dstw[_j] + (buf) * 3840) * 4, bl_src[_j] + (t) * 16);    \
    asm volatile("cp.async.commit_group;" ::: "memory");                       \
} while (0)

#define STOREA(buf, r0v, r1v) do {                                             \
    uint32_t _h0,_l0,_h1,_l1,_h2,_l2,_h3,_l3;                                  \
    splith((r0v).x, (r0v).y, _h0, _l0); splith((r0v).z, (r0v).w, _h1, _l1);    \
    splith((r1v).x, (r1v).y, _h2, _l2); splith((r1v).z, (r1v).w, _h3, _l3);    \
    uint32_t* _pH = sw + PA_H + (buf) * 2560 + arow * 20 + kw;                 \
    uint32_t* _pL = sw + PA_L + (buf) * 2560 + arow * 20 + kw;                 \
    *(uint2*)_pH = make_uint2(_h0, _h1); *(uint2*)(_pH + 2) = make_uint2(_h2, _h3); \
    *(uint2*)_pL = make_uint2(_l0, _l1); *(uint2*)(_pL + 2) = make_uint2(_l2, _l3); \
} while (0)

    const int wm = (wid & 3) * 32;
    const int wn = (wid >> 2) * 48;

    const int a_r = (lane & 7) + ((lane >> 3) & 1) * 8;
    const int a_c = ((lane >> 4) & 1) * 4;
    const uint32_t aoff0 = ((wm + a_r) * 20 + a_c) * 4;
    const uint32_t aoff1 = ((wm + 16 + a_r) * 20 + a_c) * 4;
    const int b_r = lane & 7;
    const int b_half = (lane >> 3) & 1;
    const int b_nt = (lane >> 4) & 1;
    uint32_t boff[3];
    #pragma unroll
    for (int p = 0; p < 3; p++)
        boff[p] = ((wn + (2 * p + b_nt) * 8 + b_r) * 20 + b_half * 4) * 4;

    float acc[2][6][4];
    #pragma unroll
    for (int mt = 0; mt < 2; mt++)
        #pragma unroll
        for (int nt = 0; nt < 6; nt++)
            #pragma unroll
            for (int i = 0; i < 4; i++) acc[mt][nt][i] = 0.f;

    // prologue
    float4 ar0 = *(const float4*)ag;
    float4 ar1 = *(const float4*)(ag + 4);
    STOREA(0, ar0, ar1);
    PLOADB(0, 0);
    ar0 = *(const float4*)(ag + 32);
    ar1 = *(const float4*)(ag + 36);

    #pragma unroll 2
    for (int t = 0; t < 12; t++) {
        const int buf = t & 1;
        asm volatile("cp.async.wait_group 0;" ::: "memory");
        __syncthreads();
        if (t < 11) {
            STOREA(buf ^ 1, ar0, ar1);
            PLOADB(buf ^ 1, t + 1);
            if (t < 10) {
                ar0 = *(const float4*)(ag + (t + 2) * 32);
                ar1 = *(const float4*)(ag + (t + 2) * 32 + 4);
            }
        }
        const uint32_t aBH = sb + (PA_H + buf * 2560) * 4;
        const uint32_t aBL = sb + (PA_L + buf * 2560) * 4;
        const uint32_t bBH = sb + (PB_H + buf * 3840) * 4;
        const uint32_t bBL = sb + (PB_L + buf * 3840) * 4;
        #pragma unroll
        for (int kk = 0; kk < 2; kk++) {
            uint32_t AH0[4], AH1[4], AL0[4], AL1[4];
            LDM4(AH0, aBH + aoff0 + kk * 32);
            LDM4(AH1, aBH + aoff1 + kk * 32);
            LDM4(AL0, aBL + aoff0 + kk * 32);
            LDM4(AL1, aBL + aoff1 + kk * 32);
            #pragma unroll
            for (int p = 0; p < 3; p++) {
                uint32_t BH[4], BL[4];
                LDM4(BH, bBH + boff[p] + kk * 32);
                LDM4(BL, bBL + boff[p] + kk * 32);
                // term-major across 4 independent accumulators
                mma_f16(acc[0][2*p],   AH0, BH[0], BH[1]);
                mma_f16(acc[1][2*p],   AH1, BH[0], BH[1]);
                mma_f16(acc[0][2*p+1], AH0, BH[2], BH[3]);
                mma_f16(acc[1][2*p+1], AH1, BH[2], BH[3]);
                mma_f16(acc[0][2*p],   AH0, BL[0], BL[1]);
                mma_f16(acc[1][2*p],   AH1, BL[0], BL[1]);
                mma_f16(acc[0][2*p+1], AH0, BL[2], BL[3]);
                mma_f16(acc[1][2*p+1], AH1, BL[2], BL[3]);
                mma_f16(acc[0][2*p],   AL0, BH[0], BH[1]);
                mma_f16(acc[1][2*p],   AL1, BH[0], BH[1]);
                mma_f16(acc[0][2*p+1], AL0, BH[2], BH[3]);
                mma_f16(acc[1][2*p+1], AL1, BH[2], BH[3]);
            }
        }
    }

    // ---- proj epilogue: write Q/K/V into attn smem (V transposed) ----
    {
        __half* vhh = (__half*)(sw + AV_H);
        __half* vlh = (__half*)(sw + AV_L);
        #pragma unroll
        for (int nt = 0; nt < 6; nt++) {
            int n = wn + nt * 8;
            #pragma unroll
            for (int mt = 0; mt < 2; mt++) {
                int ra = wm + mt * 16 + gr;
                int rb = ra + 8;
                if (n < 128) {
                    int base_h = (n < 64) ? AQ_H : AK_H;
                    int base_l = (n < 64) ? AQ_L : AK_L;
                    int pidx = ((n & 63) >> 1) + tg;
                    uint32_t h, l;
                    splith(acc[mt][nt][0], acc[mt][nt][1], h, l);
                    sw[base_h + ra * 36 + pidx] = h;
                    sw[base_l + ra * 36 + pidx] = l;
                    splith(acc[mt][nt][2], acc[mt][nt][3], h, l);
                    sw[base_h + rb * 36 + pidx] = h;
                    sw[base_l + rb * 36 + pidx] = l;
                } else {
                    int c = (n & 63) + 2 * tg;
                    __half2 H, L;
                    float f0, f1;
                    H = __floats2half2_rn(acc[mt][nt][0], acc[mt][nt][1]);
                    f0 = __low2float(H); f1 = __high2float(H);
                    L = __floats2half2_rn(acc[mt][nt][0] - f0, acc[mt][nt][1] - f1);
                    vhh[c * 136 + ra] = __low2half(H);  vhh[(c + 1) * 136 + ra] = __high2half(H);
                    vlh[c * 136 + ra] = __low2half(L);  vlh[(c + 1) * 136 + ra] = __high2half(L);
                    H = __floats2half2_rn(acc[mt][nt][2], acc[mt][nt][3]);
                    f0 = __low2float(H); f1 = __high2float(H);
                    L = __floats2half2_rn(acc[mt][nt][2] - f0, acc[mt][nt][3] - f1);
                    vhh[c * 136 + rb] = __low2half(H);  vhh[(c + 1) * 136 + rb] = __high2half(H);
                    vlh[c * 136 + rb] = __low2half(L);  vlh[(c + 1) * 136 + rb] = __high2half(L);
                }
            }
        }
    }
    __syncthreads();

    // ------------------------- Phase 2: attention -------------------------
    // SMSP-balanced mapping: SMSP s gets tt {s, 7-s} for both halves (18 units).
    const int pairIdx = wid & 7;
    const int half = wid >> 3;
    const int tt = (pairIdx < 4) ? pairIdx : 11 - pairIdx;
    const int t0 = 16 * tt;
    const int r0 = t0 + gr, r1 = r0 + 8;

    float sacc[8][4];
    #pragma unroll
    for (int j = 0; j < 8; j++)
        #pragma unroll
        for (int i = 0; i < 4; i++) sacc[j][i] = 0.f;

    #pragma unroll
    for (int kk = 0; kk < 4; kk++) {
        uint32_t ah[4], al[4];
        ah[0] = sw[AQ_H + r0 * 36 + 8 * kk + tg];
        ah[1] = sw[AQ_H + r1 * 36 + 8 * kk + tg];
        ah[2] = sw[AQ_H + r0 * 36 + 8 * kk + 4 + tg];
        ah[3] = sw[AQ_H + r1 * 36 + 8 * kk + 4 + tg];
        al[0] = sw[AQ_L + r0 * 36 + 8 * kk + tg];
        al[1] = sw[AQ_L + r1 * 36 + 8 * kk + tg];
        al[2] = sw[AQ_L + r0 * 36 + 8 * kk + 4 + tg];
        al[3] = sw[AQ_L + r1 * 36 + 8 * kk + 4 + tg];
        #pragma unroll
        for (int j = 0; j < 8; j++) {
            if (j <= tt) {
                int s = (2 * j + half) * 8 + gr;
                uint32_t bh0 = sw[AK_H + s * 36 + 8 * kk + tg];
                uint32_t bh1 = sw[AK_H + s * 36 + 8 * kk + 4 + tg];
                uint32_t bl0 = sw[AK_L + s * 36 + 8 * kk + tg];
                uint32_t bl1 = sw[AK_L + s * 36 + 8 * kk + 4 + tg];
                mma_f16(sacc[j], ah, bh0, bh1);
                mma_f16(sacc[j], ah, bl0, bl1);
                mma_f16(sacc[j], al, bh0, bh1);
            }
        }
    }

    const float NEG = __int_as_float(0xff800000);
    float mx0 = NEG, mx1 = NEG;
    #pragma unroll
    for (int j = 0; j < 8; j++) {
        if (j <= tt) {
            int c = (2 * j + half) * 8 + 2 * tg;
            float v0 = (c     <= r0) ? sacc[j][0] * SCALE : NEG;
            float v1 = (c + 1 <= r0) ? sacc[j][1] * SCALE : NEG;
            float v2 = (c     <= r1) ? sacc[j][2] * SCALE : NEG;
            float v3 = (c + 1 <= r1) ? sacc[j][3] * SCALE : NEG;
            sacc[j][0] = v0; sacc[j][1] = v1; sacc[j][2] = v2; sacc[j][3] = v3;
            mx0 = fmaxf(mx0, fmaxf(v0, v1));
            mx1 = fmaxf(mx1, fmaxf(v2, v3));
        }
    }
    mx0 = fmaxf(mx0, __shfl_xor_sync(0xffffffffu, mx0, 1));
    mx0 = fmaxf(mx0, __shfl_xor_sync(0xffffffffu, mx0, 2));
    mx1 = fmaxf(mx1, __shfl_xor_sync(0xffffffffu, mx1, 1));
    mx1 = fmaxf(mx1, __shfl_xor_sync(0xffffffffu, mx1, 2));
    if (tg == 0) {
        smf[PMX + half * 128 + r0] = mx0;
        smf[PMX + half * 128 + r1] = mx1;
    }
    __syncthreads();
    mx0 = fmaxf(smf[PMX + r0], smf[PMX + 128 + r0]);
    mx1 = fmaxf(smf[PMX + r1], smf[PMX + 128 + r1]);

    float s0 = 0.f, s1 = 0.f;
    #pragma unroll
    for (int j = 0; j < 8; j++) {
        if (j <= tt) {
            float p0 = __expf(sacc[j][0] - mx0);
            float p1 = __expf(sacc[j][1] - mx0);
            float p2 = __expf(sacc[j][2] - mx1);
            float p3 = __expf(sacc[j][3] - mx1);
            sacc[j][0] = p0; sacc[j][1] = p1; sacc[j][2] = p2; sacc[j][3] = p3;
            s0 += p0 + p1;  s1 += p2 + p3;
        }
    }
    s0 += __shfl_xor_sync(0xffffffffu, s0, 1);
    s0 += __shfl_xor_sync(0xffffffffu, s0, 2);
    s1 += __shfl_xor_sync(0xffffffffu, s1, 1);
    s1 += __shfl_xor_sync(0xffffffffu, s1, 2);
    if (tg == 0) {
        smf[PSUM + half * 128 + r0] = s0;
        smf[PSUM + half * 128 + r1] = s1;
    }
    __syncthreads();
    const float i0 = 1.0f / (smf[PSUM + r0] + smf[PSUM + 128 + r0]);
    const float i1 = 1.0f / (smf[PSUM + r1] + smf[PSUM + 128 + r1]);
    #pragma unroll
    for (int j = 0; j < 8; j++) {
        if (j <= tt) {
            sacc[j][0] *= i0; sacc[j][1] *= i0;
            sacc[j][2] *= i1; sacc[j][3] *= i1;
        }
    }

    // ---- PV: fuse s-tile pairs into k16 MMAs (k8 tail for odd counts) ----
    float oacc[8][4];
    #pragma unroll
    for (int ht = 0; ht < 8; ht++)
        #pragma unroll
        for (int i = 0; i < 4; i++) oacc[ht][i] = 0.f;

    #pragma unroll
    for (int jj = 0; jj < 4; jj++) {
        int j0 = 2 * jj, j1 = 2 * jj + 1;
        if (j0 <= tt) {
            int st0 = 2 * j0 + half;
            uint32_t p0h, p0l, p1h, p1l;
            splith(sacc[j0][0], sacc[j0][1], p0h, p0l);
            splith(sacc[j0][2], sacc[j0][3], p1h, p1l);
            if (j1 <= tt) {
                int st1 = st0 + 2;
                uint32_t q0h, q0l, q1h, q1l;
                splith(sacc[j1][0], sacc[j1][1], q0h, q0l);
                splith(sacc[j1][2], sacc[j1][3], q1h, q1l);
                uint32_t Ph[4] = {p0h, p1h, q0h, q1h};
                uint32_t Pl[4] = {p0l, p1l, q0l, q1l};
                #pragma unroll
                for (int ht = 0; ht < 8; ht++) {
                    int h = ht * 8 + gr;
                    uint32_t bh0 = sw[AV_H + h * 68 + 4 * st0 + tg];
                    uint32_t bh1 = sw[AV_H + h * 68 + 4 * st1 + tg];
                    uint32_t bl0 = sw[AV_L + h * 68 + 4 * st0 + tg];
                    uint32_t bl1 = sw[AV_L + h * 68 + 4 * st1 + tg];
                    mma_f16(oacc[ht], Ph, bh0, bh1);
                    mma_f16(oacc[ht], Ph, bl0, bl1);
                    mma_f16(oacc[ht], Pl, bh0, bh1);
                }
            } else {
                #pragma unroll
                for (int ht = 0; ht < 8; ht++) {
                    int h = ht * 8 + gr;
                    uint32_t bh = sw[AV_H + h * 68 + 4 * st0 + tg];
                    uint32_t bl = sw[AV_L + h * 68 + 4 * st0 + tg];
                    mma_f16_k8(oacc[ht], p0h, p1h, bh);
                    mma_f16_k8(oacc[ht], p0h, p1h, bl);
                    mma_f16_k8(oacc[ht], p0l, p1l, bh);
                }
            }
        }
    }

    if (half) {
        #pragma unroll
        for (int ht = 0; ht < 8; ht++) {
            int c = ht * 8 + 2 * tg;
            *(float2*)&smf[OPART + r0 * 66 + c] = make_float2(oacc[ht][0], oacc[ht][1]);
            *(float2*)&smf[OPART + r1 * 66 + c] = make_float2(oacc[ht][2], oacc[ht][3]);
        }
    }
    __syncthreads();
    if (!half) {
        float* ob = out + (size_t)b * TQ * HD;
        #pragma unroll
        for (int ht = 0; ht < 8; ht++) {
            int c = ht * 8 + 2 * tg;
            float2 q0 = *(float2*)&smf[OPART + r0 * 66 + c];
            float2 q1 = *(float2*)&smf[OPART + r1 * 66 + c];
            *(float2*)(ob + (size_t)r0 * HD + c) =
                make_float2(oacc[ht][0] + q0.x, oacc[ht][1] + q0.y);
            *(float2*)(ob + (size_t)r1 * HD + c) =
                make_float2(oacc[ht][2] + q1.x, oacc[ht][3] + q1.y);
        }
    }
}

// ============================================================================
extern "C" void kernel_launch(void* const* d_in, const int* in_sizes, int n_in,
                              void* d_out, int out_size)
{
    (void)in_sizes; (void)n_in; (void)out_size;
    const float* x  = (const float*)d_in[0];
    const float* Wq = (const float*)d_in[1];
    const float* Wk = (const float*)d_in[2];
    const float* Wv = (const float*)d_in[3];
    float* out = (float*)d_out;

    cudaFuncSetAttribute(fused_kernel,
                         cudaFuncAttributeMaxDynamicSharedMemorySize, FU_SMEM);

    wsplit_kernel<<<(192 * 192 + 255) / 256, 256>>>(Wq, Wk, Wv);
    fused_kernel<<<NB, 512, FU_SMEM>>>(x, out);
}

// round 9
// speedup vs baseline: 3.0175x; 1.0361x over previous
#include <cuda_runtime.h>
#include <cuda_fp16.h>
#include <cstdint>

// Problem dims
#define NB   512
#define TQ   128
#define CD   384
#define HD   64
#define SCALE 0.4082482904638631f   // 6^-0.5

// W pre-split: fp16 hi/lo pair words, layout [n=192][kpair=192]
__device__ __align__(16) uint32_t g_whi[192*192];
__device__ __align__(16) uint32_t g_wlo[192*192];

// ---------------- helpers ----------------
__device__ __forceinline__ void mma_f16(float* d, const uint32_t* a,
                                        uint32_t b0, uint32_t b1)
{
    asm("mma.sync.aligned.m16n8k16.row.col.f32.f16.f16.f32 "
        "{%0,%1,%2,%3}, {%4,%5,%6,%7}, {%8,%9}, {%0,%1,%2,%3};"
        : "+f"(d[0]), "+f"(d[1]), "+f"(d[2]), "+f"(d[3])
        : "r"(a[0]), "r"(a[1]), "r"(a[2]), "r"(a[3]), "r"(b0), "r"(b1));
}
__device__ __forceinline__ void mma_f16_k8(float* d, uint32_t a0, uint32_t a1,
                                           uint32_t b0)
{
    asm("mma.sync.aligned.m16n8k8.row.col.f32.f16.f16.f32 "
        "{%0,%1,%2,%3}, {%4,%5}, {%6}, {%0,%1,%2,%3};"
        : "+f"(d[0]), "+f"(d[1]), "+f"(d[2]), "+f"(d[3])
        : "r"(a0), "r"(a1), "r"(b0));
}
#define LDM4(r, a) \
    asm volatile("ldmatrix.sync.aligned.m8n8.x4.shared.b16 {%0,%1,%2,%3}, [%4];" \
        : "=r"((r)[0]), "=r"((r)[1]), "=r"((r)[2]), "=r"((r)[3]) : "r"(a))
#define LDM4T(r, a) \
    asm volatile("ldmatrix.sync.aligned.m8n8.x4.trans.shared.b16 {%0,%1,%2,%3}, [%4];" \
        : "=r"((r)[0]), "=r"((r)[1]), "=r"((r)[2]), "=r"((r)[3]) : "r"(a))
#define BARP(id) asm volatile("bar.sync %0, 64;" :: "r"(id) : "memory")

__device__ __forceinline__ void splith(float e0, float e1,
                                       uint32_t& h, uint32_t& l)
{
    __half2 H = __floats2half2_rn(e0, e1);
    float f0 = __low2float(H), f1 = __high2float(H);
    __half2 L = __floats2half2_rn(e0 - f0, e1 - f1);
    h = *(uint32_t*)&H;
    l = *(uint32_t*)&L;
}
__device__ __forceinline__ void cp16(uint32_t s, const void* g) {
    asm volatile("cp.async.cg.shared.global [%0], [%1], 16;" :: "r"(s), "l"(g));
}

// ============================================================================
// Kernel 0: split W -> fp16 hi/lo pair words, [n=192][kpair=192]
// ============================================================================
__global__ __launch_bounds__(256) void wsplit_kernel(
    const float* __restrict__ Wq, const float* __restrict__ Wk,
    const float* __restrict__ Wv)
{
    int idx = blockIdx.x * 256 + threadIdx.x;
    if (idx >= 192 * 192) return;
    int kp = idx / 192, n = idx % 192;        // n fastest -> coalesced reads
    const float* W = (n < 64) ? Wq : (n < 128) ? Wk : Wv;
    int c = n & 63;
    float e0 = W[(size_t)(2 * kp) * HD + c];
    float e1 = W[(size_t)(2 * kp + 1) * HD + c];
    uint32_t h, l;
    splith(e0, e1, h, l);
    g_whi[n * 192 + kp] = h;
    g_wlo[n * 192 + kp] = l;
}

// ============================================================================
// Fused kernel: one CTA per batch (512 threads, 16 warps).
// All Q/K/V tiles stored row-major [row][pair-word], stride 36 words.
// ============================================================================
// smem word offsets
#define PA_H  0          // [2][128*20]
#define PA_L  5120
#define PB_H  10240      // [2][192*20]
#define PB_L  17920
#define AQ_H  25600      // [128][36] each
#define AQ_L  30208
#define AK_H  34816
#define AK_L  39424
#define AV_H  44032
#define AV_L  48640
// overlaid on dead proj buffers:
#define PMX   0          // float [2][128]
#define PSUM  256        // float [2][128]
#define OPART 512        // float [128][66]
#define FU_SMEM (53248 * 4)   // 212,992 B

__global__ __launch_bounds__(512) void fused_kernel(
    const float* __restrict__ x, float* __restrict__ out)
{
    extern __shared__ uint32_t sw[];
    float* smf = (float*)sw;
    const uint32_t sb = (uint32_t)__cvta_generic_to_shared(sw);
    const int tid = threadIdx.x, b = blockIdx.x;
    const int lane = tid & 31, wid = tid >> 5;
    const int gr = lane >> 2, tg = lane & 3;

    // ------------------------- Phase 1: projection -------------------------
    const int arow = tid >> 2;
    const int kw   = (tid & 3) * 4;
    const float* ag = x + ((size_t)b * 128 + arow) * CD + (tid & 3) * 8;

    const uint32_t* bl_src[3];
    uint32_t bl_dstw[3];
    #pragma unroll
    for (int j = 0; j < 3; j++) {
        int id = tid + j * 512;
        int hi = (id < 768);
        int i = hi ? id : id - 768;
        int bn = i >> 2, bch = i & 3;
        bl_src[j] = (hi ? g_whi : g_wlo) + bn * 192 + bch * 4;
        bl_dstw[j] = (hi ? PB_H : PB_L) + bn * 20 + bch * 4;
    }
#define PLOADB(buf, t) do {                                                    \
    _Pragma("unroll")                                                          \
    for (int _j = 0; _j < 3; _j++)                                             \
        cp16(sb + (bl_dstw[_j] + (buf) * 3840) * 4, bl_src[_j] + (t) * 16);    \
    asm volatile("cp.async.commit_group;" ::: "memory");                       \
} while (0)

#define STOREA(buf, r0v, r1v) do {                                             \
    uint32_t _h0,_l0,_h1,_l1,_h2,_l2,_h3,_l3;                                  \
    splith((r0v).x, (r0v).y, _h0, _l0); splith((r0v).z, (r0v).w, _h1, _l1);    \
    splith((r1v).x, (r1v).y, _h2, _l2); splith((r1v).z, (r1v).w, _h3, _l3);    \
    uint32_t* _pH = sw + PA_H + (buf) * 2560 + arow * 20 + kw;                 \
    uint32_t* _pL = sw + PA_L + (buf) * 2560 + arow * 20 + kw;                 \
    *(uint2*)_pH = make_uint2(_h0, _h1); *(uint2*)(_pH + 2) = make_uint2(_h2, _h3); \
    *(uint2*)_pL = make_uint2(_l0, _l1); *(uint2*)(_pL + 2) = make_uint2(_l2, _l3); \
} while (0)

    const int wm = (wid & 3) * 32;
    const int wn = (wid >> 2) * 48;

    const int a_r = (lane & 7) + ((lane >> 3) & 1) * 8;
    const int a_c = ((lane >> 4) & 1) * 4;
    const uint32_t aoff0 = ((wm + a_r) * 20 + a_c) * 4;
    const uint32_t aoff1 = ((wm + 16 + a_r) * 20 + a_c) * 4;
    const int b_r = lane & 7;
    const int b_half = (lane >> 3) & 1;
    const int b_nt = (lane >> 4) & 1;
    uint32_t boff[3];
    #pragma unroll
    for (int p = 0; p < 3; p++)
        boff[p] = ((wn + (2 * p + b_nt) * 8 + b_r) * 20 + b_half * 4) * 4;

    float acc[2][6][4];
    #pragma unroll
    for (int mt = 0; mt < 2; mt++)
        #pragma unroll
        for (int nt = 0; nt < 6; nt++)
            #pragma unroll
            for (int i = 0; i < 4; i++) acc[mt][nt][i] = 0.f;

    float4 ar0 = *(const float4*)ag;
    float4 ar1 = *(const float4*)(ag + 4);
    STOREA(0, ar0, ar1);
    PLOADB(0, 0);
    ar0 = *(const float4*)(ag + 32);
    ar1 = *(const float4*)(ag + 36);

    #pragma unroll 2
    for (int t = 0; t < 12; t++) {
        const int buf = t & 1;
        asm volatile("cp.async.wait_group 0;" ::: "memory");
        __syncthreads();
        if (t < 11) {
            STOREA(buf ^ 1, ar0, ar1);
            PLOADB(buf ^ 1, t + 1);
            if (t < 10) {
                ar0 = *(const float4*)(ag + (t + 2) * 32);
                ar1 = *(const float4*)(ag + (t + 2) * 32 + 4);
            }
        }
        const uint32_t aBH = sb + (PA_H + buf * 2560) * 4;
        const uint32_t aBL = sb + (PA_L + buf * 2560) * 4;
        const uint32_t bBH = sb + (PB_H + buf * 3840) * 4;
        const uint32_t bBL = sb + (PB_L + buf * 3840) * 4;
        #pragma unroll
        for (int kk = 0; kk < 2; kk++) {
            uint32_t AH0[4], AH1[4], AL0[4], AL1[4];
            LDM4(AH0, aBH + aoff0 + kk * 32);
            LDM4(AH1, aBH + aoff1 + kk * 32);
            LDM4(AL0, aBL + aoff0 + kk * 32);
            LDM4(AL1, aBL + aoff1 + kk * 32);
            #pragma unroll
            for (int p = 0; p < 3; p++) {
                uint32_t BH[4], BL[4];
                LDM4(BH, bBH + boff[p] + kk * 32);
                LDM4(BL, bBL + boff[p] + kk * 32);
                mma_f16(acc[0][2*p],   AH0, BH[0], BH[1]);
                mma_f16(acc[1][2*p],   AH1, BH[0], BH[1]);
                mma_f16(acc[0][2*p+1], AH0, BH[2], BH[3]);
                mma_f16(acc[1][2*p+1], AH1, BH[2], BH[3]);
                mma_f16(acc[0][2*p],   AH0, BL[0], BL[1]);
                mma_f16(acc[1][2*p],   AH1, BL[0], BL[1]);
                mma_f16(acc[0][2*p+1], AH0, BL[2], BL[3]);
                mma_f16(acc[1][2*p+1], AH1, BL[2], BL[3]);
                mma_f16(acc[0][2*p],   AL0, BH[0], BH[1]);
                mma_f16(acc[1][2*p],   AL1, BH[0], BH[1]);
                mma_f16(acc[0][2*p+1], AL0, BH[2], BH[3]);
                mma_f16(acc[1][2*p+1], AL1, BH[2], BH[3]);
            }
        }
    }

    // ---- proj epilogue: write Q/K/V into attn smem (uniform row-major) ----
    #pragma unroll
    for (int nt = 0; nt < 6; nt++) {
        int n = wn + nt * 8;
        int base_h = (n < 64) ? AQ_H : (n < 128) ? AK_H : AV_H;
        int base_l = (n < 64) ? AQ_L : (n < 128) ? AK_L : AV_L;
        int pidx = ((n & 63) >> 1) + tg;
        #pragma unroll
        for (int mt = 0; mt < 2; mt++) {
            int ra = wm + mt * 16 + gr;
            int rb = ra + 8;
            uint32_t h, l;
            splith(acc[mt][nt][0], acc[mt][nt][1], h, l);
            sw[base_h + ra * 36 + pidx] = h;
            sw[base_l + ra * 36 + pidx] = l;
            splith(acc[mt][nt][2], acc[mt][nt][3], h, l);
            sw[base_h + rb * 36 + pidx] = h;
            sw[base_l + rb * 36 + pidx] = l;
        }
    }
    __syncthreads();

    // ------------------------- Phase 2: attention -------------------------
    const int pairIdx = wid & 7;
    const int half = wid >> 3;
    const int tt = (pairIdx < 4) ? pairIdx : 11 - pairIdx;
    const int t0 = 16 * tt;
    const int r0 = t0 + gr, r1 = r0 + 8;
    const int barid = 1 + pairIdx;

    // ldmatrix lane addresses
    // Q (A-frag): same mapping as proj A
    const uint32_t q_byte = ((t0 + a_r) * 36 + a_c) * 4;
    // K (B-frag): lanes16-31 -> second owned s-tile; jp stride 32 rows
    const uint32_t k_byte = (((half + 2 * b_nt) * 8 + b_r) * 36 + 4 * b_half) * 4;
    // V (trans B-frag): g = lane>>3; odd g -> st1 rows; g>=2 -> upper h words
    const int vg = lane >> 3;
    const uint32_t v_byte = (((half + 2 * (vg & 1)) * 8 + (lane & 7)) * 36
                             + ((vg >> 1) ? 4 : 0)) * 4;

    float sacc[8][4];
    #pragma unroll
    for (int j = 0; j < 8; j++)
        #pragma unroll
        for (int i = 0; i < 4; i++) sacc[j][i] = 0.f;

    #pragma unroll
    for (int kk = 0; kk < 4; kk++) {
        uint32_t AH[4], AL[4];
        LDM4(AH, sb + AQ_H * 4 + q_byte + kk * 32);
        LDM4(AL, sb + AQ_L * 4 + q_byte + kk * 32);
        #pragma unroll
        for (int jp = 0; jp < 4; jp++) {
            int j0 = 2 * jp, j1 = 2 * jp + 1;
            if (j0 <= tt) {
                uint32_t KH[4], KL[4];
                LDM4(KH, sb + AK_H * 4 + k_byte + jp * 4608 + kk * 32);
                LDM4(KL, sb + AK_L * 4 + k_byte + jp * 4608 + kk * 32);
                mma_f16(sacc[j0], AH, KH[0], KH[1]);
                mma_f16(sacc[j0], AH, KL[0], KL[1]);
                mma_f16(sacc[j0], AL, KH[0], KH[1]);
                if (j1 <= tt) {
                    mma_f16(sacc[j1], AH, KH[2], KH[3]);
                    mma_f16(sacc[j1], AH, KL[2], KL[3]);
                    mma_f16(sacc[j1], AL, KH[2], KH[3]);
                }
            }
        }
    }

    const float NEG = __int_as_float(0xff800000);
    float mx0 = NEG, mx1 = NEG;
    #pragma unroll
    for (int j = 0; j < 8; j++) {
        if (j <= tt) {
            int c = (2 * j + half) * 8 + 2 * tg;
            float v0 = (c     <= r0) ? sacc[j][0] * SCALE : NEG;
            float v1 = (c + 1 <= r0) ? sacc[j][1] * SCALE : NEG;
            float v2 = (c     <= r1) ? sacc[j][2] * SCALE : NEG;
            float v3 = (c + 1 <= r1) ? sacc[j][3] * SCALE : NEG;
            sacc[j][0] = v0; sacc[j][1] = v1; sacc[j][2] = v2; sacc[j][3] = v3;
            mx0 = fmaxf(mx0, fmaxf(v0, v1));
            mx1 = fmaxf(mx1, fmaxf(v2, v3));
        }
    }
    mx0 = fmaxf(mx0, __shfl_xor_sync(0xffffffffu, mx0, 1));
    mx0 = fmaxf(mx0, __shfl_xor_sync(0xffffffffu, mx0, 2));
    mx1 = fmaxf(mx1, __shfl_xor_sync(0xffffffffu, mx1, 1));
    mx1 = fmaxf(mx1, __shfl_xor_sync(0xffffffffu, mx1, 2));
    if (tg == 0) {
        smf[PMX + half * 128 + r0] = mx0;
        smf[PMX + half * 128 + r1] = mx1;
    }
    BARP(barid);
    mx0 = fmaxf(smf[PMX + r0], smf[PMX + 128 + r0]);
    mx1 = fmaxf(smf[PMX + r1], smf[PMX + 128 + r1]);

    float s0 = 0.f, s1 = 0.f;
    #pragma unroll
    for (int j = 0; j < 8; j++) {
        if (j <= tt) {
            float p0 = __expf(sacc[j][0] - mx0);
            float p1 = __expf(sacc[j][1] - mx0);
            float p2 = __expf(sacc[j][2] - mx1);
            float p3 = __expf(sacc[j][3] - mx1);
            sacc[j][0] = p0; sacc[j][1] = p1; sacc[j][2] = p2; sacc[j][3] = p3;
            s0 += p0 + p1;  s1 += p2 + p3;
        }
    }
    s0 += __shfl_xor_sync(0xffffffffu, s0, 1);
    s0 += __shfl_xor_sync(0xffffffffu, s0, 2);
    s1 += __shfl_xor_sync(0xffffffffu, s1, 1);
    s1 += __shfl_xor_sync(0xffffffffu, s1, 2);
    if (tg == 0) {
        smf[PSUM + half * 128 + r0] = s0;
        smf[PSUM + half * 128 + r1] = s1;
    }
    BARP(barid);
    const float i0 = 1.0f / (smf[PSUM + r0] + smf[PSUM + 128 + r0]);
    const float i1 = 1.0f / (smf[PSUM + r1] + smf[PSUM + 128 + r1]);
    #pragma unroll
    for (int j = 0; j < 8; j++) {
        if (j <= tt) {
            sacc[j][0] *= i0; sacc[j][1] *= i0;
            sacc[j][2] *= i1; sacc[j][3] *= i1;
        }
    }

    // ---- PV: k16 over fused s-tile pairs; B via ldmatrix.trans ----
    float oacc[8][4];
    #pragma unroll
    for (int ht = 0; ht < 8; ht++)
        #pragma unroll
        for (int i = 0; i < 4; i++) oacc[ht][i] = 0.f;

    #pragma unroll
    for (int jj = 0; jj < 4; jj++) {
        int j0 = 2 * jj, j1 = 2 * jj + 1;
        if (j0 <= tt) {
            uint32_t p0h, p0l, p1h, p1l;
            splith(sacc[j0][0], sacc[j0][1], p0h, p0l);
            splith(sacc[j0][2], sacc[j0][3], p1h, p1l);
            if (j1 <= tt) {
                uint32_t q0h, q0l, q1h, q1l;
                splith(sacc[j1][0], sacc[j1][1], q0h, q0l);
                splith(sacc[j1][2], sacc[j1][3], q1h, q1l);
                uint32_t Ph[4] = {p0h, p1h, q0h, q1h};
                uint32_t Pl[4] = {p0l, p1l, q0l, q1l};
                #pragma unroll
                for (int hp = 0; hp < 4; hp++) {
                    uint32_t VH[4], VL[4];
                    LDM4T(VH, sb + AV_H * 4 + v_byte + jj * 4608 + hp * 32);
                    LDM4T(VL, sb + AV_L * 4 + v_byte + jj * 4608 + hp * 32);
                    mma_f16(oacc[2*hp],   Ph, VH[0], VH[1]);
                    mma_f16(oacc[2*hp+1], Ph, VH[2], VH[3]);
                    mma_f16(oacc[2*hp],   Ph, VL[0], VL[1]);
                    mma_f16(oacc[2*hp+1], Ph, VL[2], VL[3]);
                    mma_f16(oacc[2*hp],   Pl, VH[0], VH[1]);
                    mma_f16(oacc[2*hp+1], Pl, VH[2], VH[3]);
                }
            } else {
                #pragma unroll
                for (int hp = 0; hp < 4; hp++) {
                    uint32_t VH[4], VL[4];
                    LDM4T(VH, sb + AV_H * 4 + v_byte + jj * 4608 + hp * 32);
                    LDM4T(VL, sb + AV_L * 4 + v_byte + jj * 4608 + hp * 32);
                    mma_f16_k8(oacc[2*hp],   p0h, p1h, VH[0]);
                    mma_f16_k8(oacc[2*hp+1], p0h, p1h, VH[2]);
                    mma_f16_k8(oacc[2*hp],   p0h, p1h, VL[0]);
                    mma_f16_k8(oacc[2*hp+1], p0h, p1h, VL[2]);
                    mma_f16_k8(oacc[2*hp],   p0l, p1l, VH[0]);
                    mma_f16_k8(oacc[2*hp+1], p0l, p1l, VH[2]);
                }
            }
        }
    }

    if (half) {
        #pragma unroll
        for (int ht = 0; ht < 8; ht++) {
            int c = ht * 8 + 2 * tg;
            *(float2*)&smf[OPART + r0 * 66 + c] = make_float2(oacc[ht][0], oacc[ht][1]);
            *(float2*)&smf[OPART + r1 * 66 + c] = make_float2(oacc[ht][2], oacc[ht][3]);
        }
    }
    BARP(barid);
    if (!half) {
        float* ob = out + (size_t)b * TQ * HD;
        #pragma unroll
        for (int ht = 0; ht < 8; ht++) {
            int c = ht * 8 + 2 * tg;
            float2 q0 = *(float2*)&smf[OPART + r0 * 66 + c];
            float2 q1 = *(float2*)&smf[OPART + r1 * 66 + c];
            *(float2*)(ob + (size_t)r0 * HD + c) =
                make_float2(oacc[ht][0] + q0.x, oacc[ht][1] + q0.y);
            *(float2*)(ob + (size_t)r1 * HD + c) =
                make_float2(oacc[ht][2] + q1.x, oacc[ht][3] + q1.y);
        }
    }
}

// ============================================================================
extern "C" void kernel_launch(void* const* d_in, const int* in_sizes, int n_in,
                              void* d_out, int out_size)
{
    (void)in_sizes; (void)n_in; (void)out_size;
    const float* x  = (const float*)d_in[0];
    const float* Wq = (const float*)d_in[1];
    const float* Wk = (const float*)d_in[2];
    const float* Wv = (const float*)d_in[3];
    float* out = (float*)d_out;

    cudaFuncSetAttribute(fused_kernel,
                         cudaFuncAttributeMaxDynamicSharedMemorySize, FU_SMEM);

    wsplit_kernel<<<(192 * 192 + 255) / 256, 256>>>(Wq, Wk, Wv);
    fused_kernel<<<NB, 512, FU_SMEM>>>(x, out);
}